// round 6
// baseline (speedup 1.0000x reference)
#include <cuda_runtime.h>
#include <cuda_bf16.h>
#include <math.h>
#include <stdint.h>

#define KDIM 1024
#define NDIM 16384
#define SUBL 64                   // sub-chunk length for the scan
#define NSUB (NDIM / SUBL)        // 256 sub-chunks per row

// Feature gate: tcgen05 only exists on the sm_103a ('a'-feature) compile pass.
#if defined(__CUDA_ARCH_FEAT_SM103_ALL)
#define TC_PATH 1
#else
#define TC_PATH 0
#endif

// ---------------------------------------------------------------------------
// Scratch (device globals: allocation-free rule)
// ---------------------------------------------------------------------------
__device__ __align__(1024) __nv_bfloat16 g_Abf[(size_t)KDIM * KDIM]; // Alpha bf16 [k][j]
__device__ __align__(1024) __nv_bfloat16 g_Gbf[(size_t)NDIM * KDIM]; // G bf16 [t][j]
__device__ float  g_Ccar[(size_t)KDIM * NSUB];   // per-subchunk carry
__device__ float  g_psum[(size_t)KDIM * NSUB];   // per-subchunk row-sum
__device__ float  g_Scar[(size_t)KDIM * NSUB];   // subchunk-start S values
__device__ float  g_Mu0[KDIM];
__device__ double g_partials[512];

// ---------------------------------------------------------------------------
// PTX helpers (sm_103a)
// ---------------------------------------------------------------------------
__device__ __forceinline__ uint32_t smem_u32(const void* p) {
    uint32_t a;
    asm("{ .reg .u64 t; cvta.to.shared.u64 t, %1; cvt.u32.u64 %0, t; }" : "=r"(a) : "l"(p));
    return a;
}
__device__ __forceinline__ uint32_t elect_one() {
    uint32_t p;
    asm volatile("{\n\t.reg .pred p;\n\telect.sync _|p, 0xFFFFFFFF;\n\tselp.b32 %0, 1, 0, p;\n\t}" : "=r"(p));
    return p;
}
#define SMEM_SWIZZLE_128B(x) ((x) ^ (((x) >> 3) & 0x70))

static __device__ constexpr uint64_t SMEM_DESC_BASE_SW128 =
    (uint64_t(2) << 61) | (uint64_t(1) << 46) | (uint64_t(64) << 32) | (uint64_t(1) << 16);
#define MAKE_SMEM_DESC(a) (SMEM_DESC_BASE_SW128 | ((uint64_t)((a) >> 4) & 0x3FFF))

#define TCGEN05_ALLOC(sm, n) \
    asm volatile("tcgen05.alloc.cta_group::1.sync.aligned.shared::cta.b32 [%0], %1;" :: "r"((uint32_t)(sm)), "r"((uint32_t)(n)) : "memory")
#define TCGEN05_DEALLOC(tm, n) \
    asm volatile("tcgen05.dealloc.cta_group::1.sync.aligned.b32 %0, %1;" :: "r"(tm), "r"((uint32_t)(n)))
#define TCGEN05_RELINQ() \
    asm volatile("tcgen05.relinquish_alloc_permit.cta_group::1.sync.aligned;")
#define TCGEN05_COMMIT(mb) \
    asm volatile("tcgen05.commit.cta_group::1.mbarrier::arrive::one.shared::cluster.b64 [%0];" :: "r"((uint32_t)(mb)) : "memory")
#define TCGEN05_WAIT_LD()  asm volatile("tcgen05.wait::ld.sync.aligned;" ::: "memory")
#define TCGEN05_FENCE_AFTER() asm volatile("tcgen05.fence::after_thread_sync;" ::: "memory")
#define TCGEN05_FENCE_BEFORE() asm volatile("tcgen05.fence::before_thread_sync;" ::: "memory")
#define FENCE_PROXY_ASYNC() asm volatile("fence.proxy.async.shared::cta;" ::: "memory")
#define MBARRIER_INIT(mb, c) \
    asm volatile("mbarrier.init.shared.b64 [%0], %1;" :: "r"((uint32_t)(mb)), "r"((uint32_t)(c)) : "memory")
#define MBARRIER_INVAL(mb) \
    asm volatile("mbarrier.inval.shared.b64 [%0];" :: "r"((uint32_t)(mb)) : "memory")

__device__ __forceinline__ void mbar_wait(uint32_t addr, uint32_t parity) {
    asm volatile(
        "{\n\t.reg .pred P;\n\t"
        "LW%=:\n\t"
        "mbarrier.try_wait.parity.acquire.cta.shared::cta.b64 P, [%0], %1, 0x989680;\n\t"
        "@!P bra LW%=;\n\t}"
        :: "r"(addr), "r"(parity) : "memory");
}

__device__ __forceinline__ void cp_async16(uint32_t dst, const void* src) {
    asm volatile("cp.async.cg.shared.global [%0], [%1], 16;" :: "r"(dst), "l"(src));
}
#define CP_COMMIT() asm volatile("cp.async.commit_group;" ::: "memory")
#define CP_WAIT2()  asm volatile("cp.async.wait_group 2;" ::: "memory")

#if TC_PATH
#define TCGEN05_LD_X32(r, tm) \
    asm volatile( \
        "tcgen05.ld.sync.aligned.32x32b.x32.b32 " \
        "{%0, %1, %2, %3, %4, %5, %6, %7, " \
        " %8, %9, %10, %11, %12, %13, %14, %15, " \
        " %16, %17, %18, %19, %20, %21, %22, %23, " \
        " %24, %25, %26, %27, %28, %29, %30, %31}, [%32];" \
        : "=r"((r)[0]),  "=r"((r)[1]),  "=r"((r)[2]),  "=r"((r)[3]), \
          "=r"((r)[4]),  "=r"((r)[5]),  "=r"((r)[6]),  "=r"((r)[7]), \
          "=r"((r)[8]),  "=r"((r)[9]),  "=r"((r)[10]), "=r"((r)[11]), \
          "=r"((r)[12]), "=r"((r)[13]), "=r"((r)[14]), "=r"((r)[15]), \
          "=r"((r)[16]), "=r"((r)[17]), "=r"((r)[18]), "=r"((r)[19]), \
          "=r"((r)[20]), "=r"((r)[21]), "=r"((r)[22]), "=r"((r)[23]), \
          "=r"((r)[24]), "=r"((r)[25]), "=r"((r)[26]), "=r"((r)[27]), \
          "=r"((r)[28]), "=r"((r)[29]), "=r"((r)[30]), "=r"((r)[31]) \
        : "r"(tm))

__device__ __forceinline__ void mma_f16_ss(uint32_t d_tmem, uint64_t a_desc,
                                           uint64_t b_desc, uint32_t idesc, bool en) {
    uint32_t e = en ? 1u : 0u;
    asm volatile(
        "{\n\t.reg .pred p;\n\t"
        "setp.ne.u32 p, %5, 0;\n\t"
        "tcgen05.mma.cta_group::1.kind::f16 [%0], %1, %2, %3, {%4, %4, %4, %4}, p;\n\t}"
        :: "r"(d_tmem), "l"(a_desc), "l"(b_desc), "r"(idesc), "r"(0u), "r"(e)
        : "memory");
}
#endif  // TC_PATH

// idesc: F32 accum, bf16 A/B, M=128, N=256
#define GEMM_IDESC 0x8400490u

// ---------------------------------------------------------------------------
// Phase 1: per-subchunk carry + row partial sums. Grid (128 tchunks, 8 kgroups),
// 256 threads. Loads a 128k x 128t obs tile COALESCED into padded SMEM, then
// thread (kk, h) runs the 64-step recurrence for subchunk 2*c+h of row kk.
// ---------------------------------------------------------------------------
#define TSTRIDE 132   // padded row stride (floats); 4k+i bank pattern, 4-way worst
#define P13_SMEM (128 * TSTRIDE * 4)

__global__ void phase1_kernel(const float* __restrict__ obs,
                              const float* __restrict__ Beta) {
    extern __shared__ float st[];
    int tid = threadIdx.x;
    int c = blockIdx.x;          // 128-wide t chunk
    int kg = blockIdx.y;

    // coalesced tile load: 4096 float4
#pragma unroll
    for (int p = 0; p < 16; p++) {
        int i4 = tid + p * 256;
        int kk = i4 >> 5;                 // 32 float4 per row
        int t4 = i4 & 31;
        float4 v = *(const float4*)(obs + (size_t)(kg * 128 + kk) * NDIM + c * 128 + t4 * 4);
        *(float4*)(st + kk * TSTRIDE + t4 * 4) = v;
    }
    __syncthreads();

    int kk = tid & 127;
    int h = tid >> 7;            // half: subchunk 2c+h
    int k = kg * 128 + kk;
    float betak = Beta[k];
    float d = expf(-betak);
    const float* row = st + kk * TSTRIDE + h * SUBL;

    float C = 0.0f, sum = 0.0f;
#pragma unroll 4
    for (int i = 0; i < SUBL; i++) {
        float o = row[i];
        C = d * (C + o);
        sum += o;
    }
    g_Ccar[(size_t)k * NSUB + c * 2 + h] = C;
    g_psum[(size_t)k * NSUB + c * 2 + h] = sum;
}

// ---------------------------------------------------------------------------
// Phase 2: serial scan of 256 subchunk carries per row + Mu0. 1024 blocks.
// ---------------------------------------------------------------------------
__global__ void phase2_kernel(const float* __restrict__ Beta) {
    __shared__ float sC[NSUB];
    __shared__ float sS[NSUB];
    __shared__ float ss[NSUB];
    int k = blockIdx.x;
    int tid = threadIdx.x;       // 256 threads
    sC[tid] = g_Ccar[(size_t)k * NSUB + tid];
    ss[tid] = g_psum[(size_t)k * NSUB + tid];
    __syncthreads();
    if (tid == 0) {
        float d = expf(-Beta[k]);
        float dl = d;
#pragma unroll
        for (int q = 0; q < 6; q++) dl *= dl;   // d^64 (~0, kept for exactness)
        float S = 0.0f;
        for (int c = 0; c < NSUB; c++) {
            sS[c] = S;
            S = dl * S + sC[c];
        }
    }
    for (int off = 128; off > 0; off >>= 1) {
        __syncthreads();
        if (tid < off) ss[tid] += ss[tid + off];
    }
    __syncthreads();
    g_Scar[(size_t)k * NSUB + tid] = sS[tid];
    if (tid == 0)
        g_Mu0[k] = ss[0] / (float)(NDIM * 10) + 1e-5f;
}

// ---------------------------------------------------------------------------
// Phase 3: emit G transposed bf16. Same tiling as phase 1; stages G through
// SMEM so global writes are coalesced u32 rows of g_Gbf[t][k].
// ---------------------------------------------------------------------------
#define P3_SMEM (P13_SMEM + 128 * 128 * 2)

__global__ void phase3_kernel(const float* __restrict__ obs,
                              const float* __restrict__ Beta) {
    extern __shared__ float st[];
    __nv_bfloat16* sg = (__nv_bfloat16*)(st + 128 * TSTRIDE);   // [t 0..127][k 0..127]
    int tid = threadIdx.x;
    int c = blockIdx.x;
    int kg = blockIdx.y;

#pragma unroll
    for (int p = 0; p < 16; p++) {
        int i4 = tid + p * 256;
        int kk = i4 >> 5;
        int t4 = i4 & 31;
        float4 v = *(const float4*)(obs + (size_t)(kg * 128 + kk) * NDIM + c * 128 + t4 * 4);
        *(float4*)(st + kk * TSTRIDE + t4 * 4) = v;
    }
    __syncthreads();

    {
        int kk = tid & 127;
        int h = tid >> 7;
        int k = kg * 128 + kk;
        float betak = Beta[k];
        float d = expf(-betak);
        float S = g_Scar[(size_t)k * NSUB + c * 2 + h];
        const float* row = st + kk * TSTRIDE + h * SUBL;
#pragma unroll 4
        for (int i = 0; i < SUBL; i++) {
            sg[(h * SUBL + i) * 128 + kk] = __float2bfloat16_rn(betak * S);
            S = d * (S + row[i]);
        }
    }
    __syncthreads();

    // coalesced writeout: 8192 u32 (two bf16 each)
    uint32_t* gout = (uint32_t*)(g_Gbf + (size_t)c * 128 * KDIM + kg * 128);
    const uint32_t* sg32 = (const uint32_t*)sg;
#pragma unroll
    for (int p = 0; p < 32; p++) {
        int idx = tid + p * 256;
        int t = idx >> 6;           // 64 u32 per 128-k row
        int k2 = idx & 63;
        gout[(size_t)t * (KDIM / 2) + k2] = sg32[t * 64 + k2];
    }
}

// ---------------------------------------------------------------------------
// Alpha -> bf16
// ---------------------------------------------------------------------------
__global__ void convA_kernel(const float* __restrict__ Alpha) {
    size_t i4 = (size_t)blockIdx.x * blockDim.x + threadIdx.x;
    float4 v = ((const float4*)Alpha)[i4];
    __nv_bfloat162 lo, hi;
    lo.x = __float2bfloat16_rn(v.x); lo.y = __float2bfloat16_rn(v.y);
    hi.x = __float2bfloat16_rn(v.z); hi.y = __float2bfloat16_rn(v.w);
    ((__nv_bfloat162*)g_Abf)[i4 * 2]     = lo;
    ((__nv_bfloat162*)g_Abf)[i4 * 2 + 1] = hi;
}

// ---------------------------------------------------------------------------
// GEMM: 128(M=k) x 256(N=t) tile, K chunk = 64, 16 chunks, 4-stage cp.async
// pipeline, per-stage mbarrier gating, fused epilogue.
// ---------------------------------------------------------------------------
#define GM 128
#define GN 256
#define GK 64
#define NCH (KDIM / GK)       // 16
#define STAGES 4

#define OFF_TPTR  0
#define OFF_MBAR  16          // four 8-byte mbarriers
#define STAGE_BYTES (16384 + 32768)          // A 16KB + B 32KB
#define OFF_A(s)  (1024 + (s) * STAGE_BYTES)
#define OFF_B(s)  (OFF_A(s) + 16384)
#define GEMM_SMEM (1024 + STAGES * STAGE_BYTES)

__device__ __forceinline__ float softplus_f(float x) {
    return (x > 20.0f) ? x : log1pf(expf(x));
}

#if TC_PATH
// async-load one K-chunk (A: 128x64, B: 256x64 bf16) into stage s
__device__ __forceinline__ void issue_loads(uint32_t smem_base, int s, int cn,
                                            int k0, int t0) {
    int tid = threadIdx.x;
    const __nv_bfloat16* asrc = g_Abf + (size_t)k0 * KDIM + cn * GK;
    const __nv_bfloat16* bsrc = g_Gbf + (size_t)t0 * KDIM + cn * GK;
#pragma unroll
    for (int p = 0; p < 4; p++) {
        int q = tid + p * 256;            // 0..1023
        int r = q >> 3;
        int cc = q & 7;
        uint32_t bo = r * 128 + cc * 16;
        cp_async16(smem_base + OFF_A(s) + SMEM_SWIZZLE_128B(bo),
                   asrc + (size_t)r * KDIM + cc * 8);
    }
#pragma unroll
    for (int p = 0; p < 8; p++) {
        int q = tid + p * 256;            // 0..2047
        int r = q >> 3;                   // 0..255
        int cc = q & 7;
        uint32_t bo = r * 128 + cc * 16;
        cp_async16(smem_base + OFF_B(s) + SMEM_SWIZZLE_128B(bo),
                   bsrc + (size_t)r * KDIM + cc * 8);
    }
}
#endif

__global__ __launch_bounds__(256, 1)
void gemm_kernel(const float* __restrict__ obs,
                 float* __restrict__ out, long long out_size) {
    extern __shared__ char smem[];
    int tid = threadIdx.x;
    int t0 = blockIdx.x * GN;
    int k0 = blockIdx.y * GM;
    const long long KN = (long long)KDIM * NDIM;
    bool full_out = (out_size >= 1 + 2 * KN);
    // bases offset 4B from aligned allocation: 32-bit stores only
    float* out_lams0 = out + 1;
    float* out_lam1  = out + 1 + KN;

#if TC_PATH
    uint32_t smem_base = smem_u32(smem);
    int wid = tid >> 5;
    int lid = tid & 31;

    if (tid == 0) {
#pragma unroll
        for (int s = 0; s < STAGES; s++)
            MBARRIER_INIT(smem_base + OFF_MBAR + s * 8, 1);
    }
    if (wid == 0) {
        TCGEN05_ALLOC(smem_base + OFF_TPTR, 256);
        TCGEN05_RELINQ();
    }
    __syncthreads();
    uint32_t tmem_base;
    asm volatile("ld.shared.b32 %0, [%1];" : "=r"(tmem_base) : "r"(smem_base + OFF_TPTR));

    // prologue: preload chunks 0..2
#pragma unroll
    for (int c = 0; c < STAGES - 1; c++) {
        issue_loads(smem_base, c, c, k0, t0);
        CP_COMMIT();
    }

    int ph[STAGES] = {0, 0, 0, 0};
    for (int c = 0; c < NCH; c++) {
        int s = c & (STAGES - 1);
        CP_WAIT2();                 // chunk c's group complete
        __syncthreads();
        FENCE_PROXY_ASYNC();
        if (wid == 0) {
            if (elect_one()) {
                uint64_t ad = MAKE_SMEM_DESC(smem_base + OFF_A(s));
                uint64_t bd = MAKE_SMEM_DESC(smem_base + OFF_B(s));
#pragma unroll
                for (int sub = 0; sub < 4; sub++)
                    mma_f16_ss(tmem_base, ad + sub * 2, bd + sub * 2, GEMM_IDESC,
                               (c > 0) || (sub > 0));
                TCGEN05_COMMIT(smem_base + OFF_MBAR + s * 8);
            }
        }
        int cn = c + STAGES - 1;
        if (cn < NCH) {
            int sn = cn & (STAGES - 1);
            if (cn >= STAGES) {      // stage previously used by chunk cn-STAGES
                mbar_wait(smem_base + OFF_MBAR + sn * 8, ph[sn]);
                ph[sn] ^= 1;
            }
            issue_loads(smem_base, sn, cn, k0, t0);
        }
        CP_COMMIT();                 // commit (possibly empty) group each iter
    }
    // drain remaining MMA completions
#pragma unroll
    for (int s = 0; s < STAGES; s++)
        mbar_wait(smem_base + OFF_MBAR + s * 8, ph[s]);
    TCGEN05_FENCE_AFTER();

    // ---- epilogue: 8 warps; rows (wid&3)*32+lid, cols (wid>>2)*128 + q*32 ----
    int k = k0 + (wid & 3) * 32 + lid;
    int coloff = (wid >> 2) * 128;
    float mu = g_Mu0[k];
    double lsum = 0.0;

#pragma unroll
    for (int q = 0; q < 4; q++) {
        uint32_t dr[32];
        TCGEN05_LD_X32(dr, tmem_base + coloff + q * 32);
        TCGEN05_WAIT_LD();
        int tb = t0 + coloff + q * 32;
        const float* orow = obs + (size_t)k * NDIM + tb;
        float* l1row = out_lam1 + (size_t)k * NDIM + tb;
        float* l0row = out_lams0 + (size_t)k * NDIM + tb;
#pragma unroll
        for (int j = 0; j < 32; j += 4) {
            float4 o = *(const float4*)(orow + j);
            float4 l1;
            l1.x = softplus_f(__uint_as_float(dr[j]));
            l1.y = softplus_f(__uint_as_float(dr[j + 1]));
            l1.z = softplus_f(__uint_as_float(dr[j + 2]));
            l1.w = softplus_f(__uint_as_float(dr[j + 3]));
            if (tb + j == 0) l1.x = 0.0f;   // t == 0 branch
            if (full_out) {
                l1row[j]     = l1.x;
                l1row[j + 1] = l1.y;
                l1row[j + 2] = l1.z;
                l1row[j + 3] = l1.w;
                l0row[j]     = mu;
                l0row[j + 1] = mu;
                l0row[j + 2] = mu;
                l0row[j + 3] = mu;
            }
            lsum += (double)(o.x * logf(mu + l1.x + 1e-5f) - mu - l1.x);
            lsum += (double)(o.y * logf(mu + l1.y + 1e-5f) - mu - l1.y);
            lsum += (double)(o.z * logf(mu + l1.z + 1e-5f) - mu - l1.z);
            lsum += (double)(o.w * logf(mu + l1.w + 1e-5f) - mu - l1.w);
        }
    }
    TCGEN05_FENCE_BEFORE();

    double* dred = (double*)(smem + OFF_A(0));
    __syncthreads();
    dred[tid] = lsum;
    __syncthreads();
    for (int off = 128; off > 0; off >>= 1) {
        if (tid < off) dred[tid] += dred[tid + off];
        __syncthreads();
    }
    if (tid == 0)
        g_partials[blockIdx.y * gridDim.x + blockIdx.x] = dred[0];

    if (tid == 0) {
#pragma unroll
        for (int s = 0; s < STAGES; s++)
            MBARRIER_INVAL(smem_base + OFF_MBAR + s * 8);
    }
    __syncthreads();
    if (wid == 0)
        TCGEN05_DEALLOC(tmem_base, 256);

#else  // ---------------- SIMT fallback (non-'a' PTX pass; never runs on bench GPU)
    int tx = tid & 15;
    int ty = tid >> 4;
    float acc[8][16];
#pragma unroll
    for (int i = 0; i < 8; i++)
#pragma unroll
        for (int j = 0; j < 16; j++) acc[i][j] = 0.0f;

    for (int jj = 0; jj < KDIM; jj++) {
        float a[8], b[16];
#pragma unroll
        for (int i = 0; i < 8; i++)
            a[i] = __bfloat162float(g_Abf[(size_t)(k0 + ty * 8 + i) * KDIM + jj]);
#pragma unroll
        for (int j = 0; j < 16; j++)
            b[j] = __bfloat162float(g_Gbf[(size_t)(t0 + tx * 16 + j) * KDIM + jj]);
#pragma unroll
        for (int i = 0; i < 8; i++)
#pragma unroll
            for (int j = 0; j < 16; j++) acc[i][j] = fmaf(a[i], b[j], acc[i][j]);
    }

    double lsum = 0.0;
#pragma unroll
    for (int i = 0; i < 8; i++) {
        int k = k0 + ty * 8 + i;
        float mu = g_Mu0[k];
#pragma unroll
        for (int j = 0; j < 16; j++) {
            int t = t0 + tx * 16 + j;
            float lam = softplus_f(acc[i][j]);
            if (t == 0) lam = 0.0f;
            size_t idx = (size_t)k * NDIM + t;
            if (full_out) {
                out_lams0[idx] = mu;
                out_lam1[idx]  = lam;
            }
            float o = obs[idx];
            lsum += (double)(o * logf(mu + lam + 1e-5f) - mu - lam);
        }
    }
    double* dred = (double*)smem;
    dred[tid] = lsum;
    __syncthreads();
    for (int off = 128; off > 0; off >>= 1) {
        if (tid < off) dred[tid] += dred[tid + off];
        __syncthreads();
    }
    if (tid == 0)
        g_partials[blockIdx.y * gridDim.x + blockIdx.x] = dred[0];
#endif
}

// ---------------------------------------------------------------------------
// Final reduction of 512 double partials -> out[0]
// ---------------------------------------------------------------------------
__global__ void final_reduce_kernel(float* __restrict__ out) {
    __shared__ double dred[256];
    int tid = threadIdx.x;
    double s = 0.0;
    for (int i = tid; i < 512; i += 256) s += g_partials[i];
    dred[tid] = s;
    __syncthreads();
    for (int off = 128; off > 0; off >>= 1) {
        if (tid < off) dred[tid] += dred[tid + off];
        __syncthreads();
    }
    if (tid == 0) out[0] = (float)dred[0];
}

// ---------------------------------------------------------------------------
extern "C" void kernel_launch(void* const* d_in, const int* in_sizes, int n_in,
                              void* d_out, int out_size) {
    const float* obs   = (const float*)d_in[0];   // [K, N]
    const float* Beta  = (const float*)d_in[1];   // [K]
    const float* Alpha = (const float*)d_in[2];   // [K, K]
    float* out = (float*)d_out;

    cudaFuncSetAttribute(gemm_kernel,
                         cudaFuncAttributeMaxDynamicSharedMemorySize, GEMM_SMEM);
    cudaFuncSetAttribute(phase1_kernel,
                         cudaFuncAttributeMaxDynamicSharedMemorySize, P13_SMEM);
    cudaFuncSetAttribute(phase3_kernel,
                         cudaFuncAttributeMaxDynamicSharedMemorySize, P3_SMEM);

    phase1_kernel<<<dim3(NDIM / 128, KDIM / 128), 256, P13_SMEM>>>(obs, Beta);
    convA_kernel<<<KDIM, 256>>>(Alpha);
    phase2_kernel<<<KDIM, NSUB>>>(Beta);
    phase3_kernel<<<dim3(NDIM / 128, KDIM / 128), 256, P3_SMEM>>>(obs, Beta);

    dim3 grid(NDIM / GN, KDIM / GM);   // (64, 8)
    gemm_kernel<<<grid, 256, GEMM_SMEM>>>(obs, out, (long long)out_size);

    final_reduce_kernel<<<1, 256>>>(out);
}

// round 7
// speedup vs baseline: 1.3819x; 1.3819x over previous
#include <cuda_runtime.h>
#include <cuda_bf16.h>
#include <math.h>
#include <stdint.h>

#define KDIM 1024
#define NDIM 16384
#define SUBL 64                   // sub-chunk length for the scan
#define NSUB (NDIM / SUBL)        // 256 sub-chunks per row

// Feature gate: tcgen05 only exists on the sm_103a ('a'-feature) compile pass.
#if defined(__CUDA_ARCH_FEAT_SM103_ALL)
#define TC_PATH 1
#else
#define TC_PATH 0
#endif

// ---------------------------------------------------------------------------
// Scratch (device globals: allocation-free rule)
// ---------------------------------------------------------------------------
__device__ __align__(1024) __nv_bfloat16 g_Abf[(size_t)KDIM * KDIM]; // Alpha bf16 [k][j]
__device__ __align__(1024) __nv_bfloat16 g_Gbf[(size_t)NDIM * KDIM]; // G bf16 [t][j]
__device__ float  g_Ccar[(size_t)KDIM * NSUB];   // per-subchunk carry
__device__ float  g_psum[(size_t)KDIM * NSUB];   // per-subchunk row-sum
__device__ float  g_Scar[(size_t)KDIM * NSUB];   // subchunk-start S values
__device__ float  g_Mu0[KDIM];
__device__ double g_partials[1024];

// ---------------------------------------------------------------------------
// PTX helpers (sm_103a)
// ---------------------------------------------------------------------------
__device__ __forceinline__ uint32_t smem_u32(const void* p) {
    uint32_t a;
    asm("{ .reg .u64 t; cvta.to.shared.u64 t, %1; cvt.u32.u64 %0, t; }" : "=r"(a) : "l"(p));
    return a;
}
__device__ __forceinline__ uint32_t elect_one() {
    uint32_t p;
    asm volatile("{\n\t.reg .pred p;\n\telect.sync _|p, 0xFFFFFFFF;\n\tselp.b32 %0, 1, 0, p;\n\t}" : "=r"(p));
    return p;
}
#define SMEM_SWIZZLE_128B(x) ((x) ^ (((x) >> 3) & 0x70))

static __device__ constexpr uint64_t SMEM_DESC_BASE_SW128 =
    (uint64_t(2) << 61) | (uint64_t(1) << 46) | (uint64_t(64) << 32) | (uint64_t(1) << 16);
#define MAKE_SMEM_DESC(a) (SMEM_DESC_BASE_SW128 | ((uint64_t)((a) >> 4) & 0x3FFF))

#define TCGEN05_ALLOC(sm, n) \
    asm volatile("tcgen05.alloc.cta_group::1.sync.aligned.shared::cta.b32 [%0], %1;" :: "r"((uint32_t)(sm)), "r"((uint32_t)(n)) : "memory")
#define TCGEN05_DEALLOC(tm, n) \
    asm volatile("tcgen05.dealloc.cta_group::1.sync.aligned.b32 %0, %1;" :: "r"(tm), "r"((uint32_t)(n)))
#define TCGEN05_RELINQ() \
    asm volatile("tcgen05.relinquish_alloc_permit.cta_group::1.sync.aligned;")
#define TCGEN05_COMMIT(mb) \
    asm volatile("tcgen05.commit.cta_group::1.mbarrier::arrive::one.shared::cluster.b64 [%0];" :: "r"((uint32_t)(mb)) : "memory")
#define TCGEN05_WAIT_LD()  asm volatile("tcgen05.wait::ld.sync.aligned;" ::: "memory")
#define TCGEN05_FENCE_AFTER() asm volatile("tcgen05.fence::after_thread_sync;" ::: "memory")
#define TCGEN05_FENCE_BEFORE() asm volatile("tcgen05.fence::before_thread_sync;" ::: "memory")
#define FENCE_PROXY_ASYNC() asm volatile("fence.proxy.async.shared::cta;" ::: "memory")
#define MBARRIER_INIT(mb, c) \
    asm volatile("mbarrier.init.shared.b64 [%0], %1;" :: "r"((uint32_t)(mb)), "r"((uint32_t)(c)) : "memory")
#define MBARRIER_INVAL(mb) \
    asm volatile("mbarrier.inval.shared.b64 [%0];" :: "r"((uint32_t)(mb)) : "memory")

__device__ __forceinline__ void mbar_wait(uint32_t addr, uint32_t parity) {
    asm volatile(
        "{\n\t.reg .pred P;\n\t"
        "LW%=:\n\t"
        "mbarrier.try_wait.parity.acquire.cta.shared::cta.b64 P, [%0], %1, 0x989680;\n\t"
        "@!P bra LW%=;\n\t}"
        :: "r"(addr), "r"(parity) : "memory");
}

__device__ __forceinline__ void cp_async16(uint32_t dst, const void* src) {
    asm volatile("cp.async.cg.shared.global [%0], [%1], 16;" :: "r"(dst), "l"(src));
}
#define CP_COMMIT() asm volatile("cp.async.commit_group;" ::: "memory")
#define CP_WAIT(n)  asm volatile("cp.async.wait_group %0;" :: "n"(n) : "memory")

#if TC_PATH
#define TCGEN05_LD_X32(r, tm) \
    asm volatile( \
        "tcgen05.ld.sync.aligned.32x32b.x32.b32 " \
        "{%0, %1, %2, %3, %4, %5, %6, %7, " \
        " %8, %9, %10, %11, %12, %13, %14, %15, " \
        " %16, %17, %18, %19, %20, %21, %22, %23, " \
        " %24, %25, %26, %27, %28, %29, %30, %31}, [%32];" \
        : "=r"((r)[0]),  "=r"((r)[1]),  "=r"((r)[2]),  "=r"((r)[3]), \
          "=r"((r)[4]),  "=r"((r)[5]),  "=r"((r)[6]),  "=r"((r)[7]), \
          "=r"((r)[8]),  "=r"((r)[9]),  "=r"((r)[10]), "=r"((r)[11]), \
          "=r"((r)[12]), "=r"((r)[13]), "=r"((r)[14]), "=r"((r)[15]), \
          "=r"((r)[16]), "=r"((r)[17]), "=r"((r)[18]), "=r"((r)[19]), \
          "=r"((r)[20]), "=r"((r)[21]), "=r"((r)[22]), "=r"((r)[23]), \
          "=r"((r)[24]), "=r"((r)[25]), "=r"((r)[26]), "=r"((r)[27]), \
          "=r"((r)[28]), "=r"((r)[29]), "=r"((r)[30]), "=r"((r)[31]) \
        : "r"(tm))

__device__ __forceinline__ void mma_f16_ss(uint32_t d_tmem, uint64_t a_desc,
                                           uint64_t b_desc, uint32_t idesc, bool en) {
    uint32_t e = en ? 1u : 0u;
    asm volatile(
        "{\n\t.reg .pred p;\n\t"
        "setp.ne.u32 p, %5, 0;\n\t"
        "tcgen05.mma.cta_group::1.kind::f16 [%0], %1, %2, %3, {%4, %4, %4, %4}, p;\n\t}"
        :: "r"(d_tmem), "l"(a_desc), "l"(b_desc), "r"(idesc), "r"(0u), "r"(e)
        : "memory");
}
#endif  // TC_PATH

// idesc: F32 accum, bf16 A/B, M=128, N=128
#define GEMM_IDESC 0x8200490u

// ---------------------------------------------------------------------------
// Phase 1: per-subchunk carry + row partial sums (coalesced tile load).
// ---------------------------------------------------------------------------
#define TSTRIDE 132
#define P13_SMEM (128 * TSTRIDE * 4)

__global__ void phase1_kernel(const float* __restrict__ obs,
                              const float* __restrict__ Beta) {
    extern __shared__ float st[];
    int tid = threadIdx.x;
    int c = blockIdx.x;          // 128-wide t chunk
    int kg = blockIdx.y;

#pragma unroll
    for (int p = 0; p < 16; p++) {
        int i4 = tid + p * 256;
        int kk = i4 >> 5;
        int t4 = i4 & 31;
        float4 v = *(const float4*)(obs + (size_t)(kg * 128 + kk) * NDIM + c * 128 + t4 * 4);
        *(float4*)(st + kk * TSTRIDE + t4 * 4) = v;
    }
    __syncthreads();

    int kk = tid & 127;
    int h = tid >> 7;
    int k = kg * 128 + kk;
    float betak = Beta[k];
    float d = expf(-betak);
    const float* row = st + kk * TSTRIDE + h * SUBL;

    float C = 0.0f, sum = 0.0f;
#pragma unroll 4
    for (int i = 0; i < SUBL; i++) {
        float o = row[i];
        C = d * (C + o);
        sum += o;
    }
    g_Ccar[(size_t)k * NSUB + c * 2 + h] = C;
    g_psum[(size_t)k * NSUB + c * 2 + h] = sum;
}

// ---------------------------------------------------------------------------
// Phase 2: serial scan of subchunk carries per row + Mu0.
// ---------------------------------------------------------------------------
__global__ void phase2_kernel(const float* __restrict__ Beta) {
    __shared__ float sC[NSUB];
    __shared__ float sS[NSUB];
    __shared__ float ss[NSUB];
    int k = blockIdx.x;
    int tid = threadIdx.x;
    sC[tid] = g_Ccar[(size_t)k * NSUB + tid];
    ss[tid] = g_psum[(size_t)k * NSUB + tid];
    __syncthreads();
    if (tid == 0) {
        float d = expf(-Beta[k]);
        float dl = d;
#pragma unroll
        for (int q = 0; q < 6; q++) dl *= dl;   // d^64 (~0, kept for exactness)
        float S = 0.0f;
        for (int c = 0; c < NSUB; c++) {
            sS[c] = S;
            S = dl * S + sC[c];
        }
    }
    for (int off = 128; off > 0; off >>= 1) {
        __syncthreads();
        if (tid < off) ss[tid] += ss[tid + off];
    }
    __syncthreads();
    g_Scar[(size_t)k * NSUB + tid] = sS[tid];
    if (tid == 0)
        g_Mu0[k] = ss[0] / (float)(NDIM * 10) + 1e-5f;
}

// ---------------------------------------------------------------------------
// Phase 3: emit G transposed bf16 via SMEM staging (coalesced in and out).
// ---------------------------------------------------------------------------
#define P3_SMEM (P13_SMEM + 128 * 128 * 2)

__global__ void phase3_kernel(const float* __restrict__ obs,
                              const float* __restrict__ Beta) {
    extern __shared__ float st[];
    __nv_bfloat16* sg = (__nv_bfloat16*)(st + 128 * TSTRIDE);
    int tid = threadIdx.x;
    int c = blockIdx.x;
    int kg = blockIdx.y;

#pragma unroll
    for (int p = 0; p < 16; p++) {
        int i4 = tid + p * 256;
        int kk = i4 >> 5;
        int t4 = i4 & 31;
        float4 v = *(const float4*)(obs + (size_t)(kg * 128 + kk) * NDIM + c * 128 + t4 * 4);
        *(float4*)(st + kk * TSTRIDE + t4 * 4) = v;
    }
    __syncthreads();

    {
        int kk = tid & 127;
        int h = tid >> 7;
        int k = kg * 128 + kk;
        float betak = Beta[k];
        float d = expf(-betak);
        float S = g_Scar[(size_t)k * NSUB + c * 2 + h];
        const float* row = st + kk * TSTRIDE + h * SUBL;
#pragma unroll 4
        for (int i = 0; i < SUBL; i++) {
            sg[(h * SUBL + i) * 128 + kk] = __float2bfloat16_rn(betak * S);
            S = d * (S + row[i]);
        }
    }
    __syncthreads();

    uint32_t* gout = (uint32_t*)(g_Gbf + (size_t)c * 128 * KDIM + kg * 128);
    const uint32_t* sg32 = (const uint32_t*)sg;
#pragma unroll
    for (int p = 0; p < 32; p++) {
        int idx = tid + p * 256;
        int t = idx >> 6;
        int k2 = idx & 63;
        gout[(size_t)t * (KDIM / 2) + k2] = sg32[t * 64 + k2];
    }
}

// ---------------------------------------------------------------------------
// Alpha -> bf16
// ---------------------------------------------------------------------------
__global__ void convA_kernel(const float* __restrict__ Alpha) {
    size_t i4 = (size_t)blockIdx.x * blockDim.x + threadIdx.x;
    float4 v = ((const float4*)Alpha)[i4];
    __nv_bfloat162 lo, hi;
    lo.x = __float2bfloat16_rn(v.x); lo.y = __float2bfloat16_rn(v.y);
    hi.x = __float2bfloat16_rn(v.z); hi.y = __float2bfloat16_rn(v.w);
    ((__nv_bfloat162*)g_Abf)[i4 * 2]     = lo;
    ((__nv_bfloat162*)g_Abf)[i4 * 2 + 1] = hi;
}

// ---------------------------------------------------------------------------
// GEMM: 128x128 tile, GK=64, 16 chunks, 3-stage cp.async pipeline, occ 2,
// fused epilogue with fp32 per-thread loglik accumulation.
// ---------------------------------------------------------------------------
#define GM 128
#define GN 128
#define GK 64
#define NCH (KDIM / GK)       // 16
#define STAGES 3

#define OFF_TPTR  0
#define OFF_MBAR  16          // three 8-byte mbarriers
#define STAGE_BYTES 32768                    // A 16KB + B 16KB
#define OFF_A(s)  (1024 + (s) * STAGE_BYTES)
#define OFF_B(s)  (OFF_A(s) + 16384)
#define GEMM_SMEM (1024 + STAGES * STAGE_BYTES)   // 99328 -> occ 2

__device__ __forceinline__ float softplus_f(float x) {
    return (x > 20.0f) ? x : log1pf(expf(x));
}

#if TC_PATH
// async-load one K-chunk (A: 128x64, B: 128x64 bf16) into stage s
__device__ __forceinline__ void issue_loads(uint32_t smem_base, int s, int cn,
                                            int k0, int t0) {
    int tid = threadIdx.x;
    const __nv_bfloat16* asrc = g_Abf + (size_t)k0 * KDIM + cn * GK;
    const __nv_bfloat16* bsrc = g_Gbf + (size_t)t0 * KDIM + cn * GK;
#pragma unroll
    for (int p = 0; p < 4; p++) {
        int q = tid + p * 256;            // 0..1023
        int r = q >> 3;
        int cc = q & 7;
        uint32_t sw = SMEM_SWIZZLE_128B(r * 128 + cc * 16);
        cp_async16(smem_base + OFF_A(s) + sw, asrc + (size_t)r * KDIM + cc * 8);
        cp_async16(smem_base + OFF_B(s) + sw, bsrc + (size_t)r * KDIM + cc * 8);
    }
}
#endif

__global__ __launch_bounds__(256, 2)
void gemm_kernel(const float* __restrict__ obs,
                 float* __restrict__ out, long long out_size) {
    extern __shared__ char smem[];
    int tid = threadIdx.x;
    int t0 = blockIdx.x * GN;
    int k0 = blockIdx.y * GM;
    const long long KN = (long long)KDIM * NDIM;
    bool full_out = (out_size >= 1 + 2 * KN);
    // bases offset 4B from aligned allocation: 32-bit stores only
    float* out_lams0 = out + 1;
    float* out_lam1  = out + 1 + KN;

#if TC_PATH
    uint32_t smem_base = smem_u32(smem);
    int wid = tid >> 5;
    int lid = tid & 31;

    if (tid == 0) {
#pragma unroll
        for (int s = 0; s < STAGES; s++)
            MBARRIER_INIT(smem_base + OFF_MBAR + s * 8, 1);
    }
    if (wid == 0) {
        TCGEN05_ALLOC(smem_base + OFF_TPTR, 128);
        TCGEN05_RELINQ();
    }
    __syncthreads();
    uint32_t tmem_base;
    asm volatile("ld.shared.b32 %0, [%1];" : "=r"(tmem_base) : "r"(smem_base + OFF_TPTR));

    // prologue: preload chunks 0, 1
#pragma unroll
    for (int c = 0; c < STAGES - 1; c++) {
        issue_loads(smem_base, c, c, k0, t0);
        CP_COMMIT();
    }

    int ph[STAGES] = {0, 0, 0};
    for (int c = 0; c < NCH; c++) {
        int s = c - (c / STAGES) * STAGES;          // c % 3
        if (c == NCH - 1) { CP_WAIT(0); } else { CP_WAIT(1); }
        __syncthreads();
        FENCE_PROXY_ASYNC();
        if (wid == 0) {
            if (elect_one()) {
                uint64_t ad = MAKE_SMEM_DESC(smem_base + OFF_A(s));
                uint64_t bd = MAKE_SMEM_DESC(smem_base + OFF_B(s));
#pragma unroll
                for (int sub = 0; sub < 4; sub++)
                    mma_f16_ss(tmem_base, ad + sub * 2, bd + sub * 2, GEMM_IDESC,
                               (c > 0) || (sub > 0));
                TCGEN05_COMMIT(smem_base + OFF_MBAR + s * 8);
            }
        }
        int cn = c + STAGES - 1;
        if (cn < NCH) {
            int sn = cn - (cn / STAGES) * STAGES;
            if (c >= 1) {            // stage sn last used by chunk c-1's MMA
                mbar_wait(smem_base + OFF_MBAR + sn * 8, ph[sn]);
                ph[sn] ^= 1;
            }
            issue_loads(smem_base, sn, cn, k0, t0);
            CP_COMMIT();
        }
    }
    // drain MMAs of the last 3 chunks (13, 14, 15)
#pragma unroll
    for (int c = NCH - STAGES; c < NCH; c++) {
        int s = c - (c / STAGES) * STAGES;
        mbar_wait(smem_base + OFF_MBAR + s * 8, ph[s]);
        ph[s] ^= 1;
    }
    TCGEN05_FENCE_AFTER();

    // ---- epilogue: warp w -> rows (w&3)*32+lid, cols (w>>2)*64 + half*32 ----
    int k = k0 + (wid & 3) * 32 + lid;
    int coloff = (wid >> 2) * 64;
    float mu = g_Mu0[k];
    float lsum = 0.0f;    // fp32: 64 terms per thread, well within tolerance

#pragma unroll
    for (int half = 0; half < 2; half++) {
        uint32_t dr[32];
        TCGEN05_LD_X32(dr, tmem_base + coloff + half * 32);
        TCGEN05_WAIT_LD();
        int tb = t0 + coloff + half * 32;
        const float* orow = obs + (size_t)k * NDIM + tb;
        float* l1row = out_lam1 + (size_t)k * NDIM + tb;
        float* l0row = out_lams0 + (size_t)k * NDIM + tb;
#pragma unroll
        for (int j = 0; j < 32; j += 4) {
            float4 o = *(const float4*)(orow + j);
            float4 l1;
            l1.x = softplus_f(__uint_as_float(dr[j]));
            l1.y = softplus_f(__uint_as_float(dr[j + 1]));
            l1.z = softplus_f(__uint_as_float(dr[j + 2]));
            l1.w = softplus_f(__uint_as_float(dr[j + 3]));
            if (tb + j == 0) l1.x = 0.0f;   // t == 0 branch
            if (full_out) {
                l1row[j]     = l1.x;
                l1row[j + 1] = l1.y;
                l1row[j + 2] = l1.z;
                l1row[j + 3] = l1.w;
                l0row[j]     = mu;
                l0row[j + 1] = mu;
                l0row[j + 2] = mu;
                l0row[j + 3] = mu;
            }
            lsum += o.x * logf(mu + l1.x + 1e-5f) - mu - l1.x;
            lsum += o.y * logf(mu + l1.y + 1e-5f) - mu - l1.y;
            lsum += o.z * logf(mu + l1.z + 1e-5f) - mu - l1.z;
            lsum += o.w * logf(mu + l1.w + 1e-5f) - mu - l1.w;
        }
    }
    TCGEN05_FENCE_BEFORE();

    double* dred = (double*)(smem + OFF_A(0));
    __syncthreads();
    dred[tid] = (double)lsum;
    __syncthreads();
    for (int off = 128; off > 0; off >>= 1) {
        if (tid < off) dred[tid] += dred[tid + off];
        __syncthreads();
    }
    if (tid == 0)
        g_partials[blockIdx.y * gridDim.x + blockIdx.x] = dred[0];

    if (tid == 0) {
#pragma unroll
        for (int s = 0; s < STAGES; s++)
            MBARRIER_INVAL(smem_base + OFF_MBAR + s * 8);
    }
    __syncthreads();
    if (wid == 0)
        TCGEN05_DEALLOC(tmem_base, 128);

#else  // ---------------- SIMT fallback (non-'a' PTX pass; never runs on bench GPU)
    int tx = tid & 15;
    int ty = tid >> 4;
    float acc[8][8];
#pragma unroll
    for (int i = 0; i < 8; i++)
#pragma unroll
        for (int j = 0; j < 8; j++) acc[i][j] = 0.0f;

    for (int jj = 0; jj < KDIM; jj++) {
        float a[8], b[8];
#pragma unroll
        for (int i = 0; i < 8; i++)
            a[i] = __bfloat162float(g_Abf[(size_t)(k0 + ty * 8 + i) * KDIM + jj]);
#pragma unroll
        for (int j = 0; j < 8; j++)
            b[j] = __bfloat162float(g_Gbf[(size_t)(t0 + tx * 8 + j) * KDIM + jj]);
#pragma unroll
        for (int i = 0; i < 8; i++)
#pragma unroll
            for (int j = 0; j < 8; j++) acc[i][j] = fmaf(a[i], b[j], acc[i][j]);
    }

    float lsum = 0.0f;
#pragma unroll
    for (int i = 0; i < 8; i++) {
        int k = k0 + ty * 8 + i;
        float mu = g_Mu0[k];
#pragma unroll
        for (int j = 0; j < 8; j++) {
            int t = t0 + tx * 8 + j;
            float lam = softplus_f(acc[i][j]);
            if (t == 0) lam = 0.0f;
            size_t idx = (size_t)k * NDIM + t;
            if (full_out) {
                out_lams0[idx] = mu;
                out_lam1[idx]  = lam;
            }
            float o = obs[idx];
            lsum += o * logf(mu + lam + 1e-5f) - mu - lam;
        }
    }
    double* dred = (double*)smem;
    dred[tid] = (double)lsum;
    __syncthreads();
    for (int off = 128; off > 0; off >>= 1) {
        if (tid < off) dred[tid] += dred[tid + off];
        __syncthreads();
    }
    if (tid == 0)
        g_partials[blockIdx.y * gridDim.x + blockIdx.x] = dred[0];
#endif
}

// ---------------------------------------------------------------------------
// Final reduction of 1024 double partials -> out[0]
// ---------------------------------------------------------------------------
__global__ void final_reduce_kernel(float* __restrict__ out) {
    __shared__ double dred[256];
    int tid = threadIdx.x;
    double s = 0.0;
    for (int i = tid; i < 1024; i += 256) s += g_partials[i];
    dred[tid] = s;
    __syncthreads();
    for (int off = 128; off > 0; off >>= 1) {
        if (tid < off) dred[tid] += dred[tid + off];
        __syncthreads();
    }
    if (tid == 0) out[0] = (float)dred[0];
}

// ---------------------------------------------------------------------------
extern "C" void kernel_launch(void* const* d_in, const int* in_sizes, int n_in,
                              void* d_out, int out_size) {
    const float* obs   = (const float*)d_in[0];   // [K, N]
    const float* Beta  = (const float*)d_in[1];   // [K]
    const float* Alpha = (const float*)d_in[2];   // [K, K]
    float* out = (float*)d_out;

    cudaFuncSetAttribute(gemm_kernel,
                         cudaFuncAttributeMaxDynamicSharedMemorySize, GEMM_SMEM);
    cudaFuncSetAttribute(phase1_kernel,
                         cudaFuncAttributeMaxDynamicSharedMemorySize, P13_SMEM);
    cudaFuncSetAttribute(phase3_kernel,
                         cudaFuncAttributeMaxDynamicSharedMemorySize, P3_SMEM);

    phase1_kernel<<<dim3(NDIM / 128, KDIM / 128), 256, P13_SMEM>>>(obs, Beta);
    convA_kernel<<<KDIM, 256>>>(Alpha);
    phase2_kernel<<<KDIM, NSUB>>>(Beta);
    phase3_kernel<<<dim3(NDIM / 128, KDIM / 128), 256, P3_SMEM>>>(obs, Beta);

    dim3 grid(NDIM / GN, KDIM / GM);   // (128, 8)
    gemm_kernel<<<grid, 256, GEMM_SMEM>>>(obs, out, (long long)out_size);

    final_reduce_kernel<<<1, 256>>>(out);
}

// round 8
// speedup vs baseline: 1.4442x; 1.0451x over previous
#include <cuda_runtime.h>
#include <cuda_bf16.h>
#include <math.h>
#include <stdint.h>

#define KDIM 1024
#define NDIM 16384
#define SUBL 64                   // sub-chunk length for the scan
#define NSUB (NDIM / SUBL)        // 256 sub-chunks per row

// Feature gate: tcgen05 only exists on the sm_103a ('a'-feature) compile pass.
#if defined(__CUDA_ARCH_FEAT_SM103_ALL)
#define TC_PATH 1
#else
#define TC_PATH 0
#endif

// ---------------------------------------------------------------------------
// Scratch (device globals: allocation-free rule)
// ---------------------------------------------------------------------------
__device__ __align__(1024) __nv_bfloat16 g_Abf[(size_t)KDIM * KDIM]; // Alpha bf16 [k][j]
__device__ __align__(1024) __nv_bfloat16 g_Gbf[(size_t)NDIM * KDIM]; // G bf16 [t][j]
__device__ float  g_Ccar[(size_t)KDIM * NSUB];   // per-subchunk carry
__device__ float  g_psum[(size_t)KDIM * NSUB];   // per-subchunk row-sum
__device__ float  g_Scar[(size_t)KDIM * NSUB];   // subchunk-start S values
__device__ float  g_Mu0[KDIM];
__device__ double g_partials[1024];

// ---------------------------------------------------------------------------
// PTX helpers (sm_103a)
// ---------------------------------------------------------------------------
__device__ __forceinline__ uint32_t smem_u32(const void* p) {
    uint32_t a;
    asm("{ .reg .u64 t; cvta.to.shared.u64 t, %1; cvt.u32.u64 %0, t; }" : "=r"(a) : "l"(p));
    return a;
}
__device__ __forceinline__ uint32_t elect_one() {
    uint32_t p;
    asm volatile("{\n\t.reg .pred p;\n\telect.sync _|p, 0xFFFFFFFF;\n\tselp.b32 %0, 1, 0, p;\n\t}" : "=r"(p));
    return p;
}
#define SMEM_SWIZZLE_128B(x) ((x) ^ (((x) >> 3) & 0x70))

static __device__ constexpr uint64_t SMEM_DESC_BASE_SW128 =
    (uint64_t(2) << 61) | (uint64_t(1) << 46) | (uint64_t(64) << 32) | (uint64_t(1) << 16);
#define MAKE_SMEM_DESC(a) (SMEM_DESC_BASE_SW128 | ((uint64_t)((a) >> 4) & 0x3FFF))

#define TCGEN05_ALLOC(sm, n) \
    asm volatile("tcgen05.alloc.cta_group::1.sync.aligned.shared::cta.b32 [%0], %1;" :: "r"((uint32_t)(sm)), "r"((uint32_t)(n)) : "memory")
#define TCGEN05_DEALLOC(tm, n) \
    asm volatile("tcgen05.dealloc.cta_group::1.sync.aligned.b32 %0, %1;" :: "r"(tm), "r"((uint32_t)(n)))
#define TCGEN05_RELINQ() \
    asm volatile("tcgen05.relinquish_alloc_permit.cta_group::1.sync.aligned;")
#define TCGEN05_COMMIT(mb) \
    asm volatile("tcgen05.commit.cta_group::1.mbarrier::arrive::one.shared::cluster.b64 [%0];" :: "r"((uint32_t)(mb)) : "memory")
#define TCGEN05_WAIT_LD()  asm volatile("tcgen05.wait::ld.sync.aligned;" ::: "memory")
#define TCGEN05_FENCE_AFTER() asm volatile("tcgen05.fence::after_thread_sync;" ::: "memory")
#define TCGEN05_FENCE_BEFORE() asm volatile("tcgen05.fence::before_thread_sync;" ::: "memory")
#define FENCE_PROXY_ASYNC() asm volatile("fence.proxy.async.shared::cta;" ::: "memory")
#define MBARRIER_INIT(mb, c) \
    asm volatile("mbarrier.init.shared.b64 [%0], %1;" :: "r"((uint32_t)(mb)), "r"((uint32_t)(c)) : "memory")
#define MBARRIER_INVAL(mb) \
    asm volatile("mbarrier.inval.shared.b64 [%0];" :: "r"((uint32_t)(mb)) : "memory")

__device__ __forceinline__ void mbar_wait(uint32_t addr, uint32_t parity) {
    asm volatile(
        "{\n\t.reg .pred P;\n\t"
        "LW%=:\n\t"
        "mbarrier.try_wait.parity.acquire.cta.shared::cta.b64 P, [%0], %1, 0x989680;\n\t"
        "@!P bra LW%=;\n\t}"
        :: "r"(addr), "r"(parity) : "memory");
}

__device__ __forceinline__ void cp_async16(uint32_t dst, const void* src) {
    asm volatile("cp.async.cg.shared.global [%0], [%1], 16;" :: "r"(dst), "l"(src));
}
#define CP_COMMIT() asm volatile("cp.async.commit_group;" ::: "memory")
#define CP_WAIT(n)  asm volatile("cp.async.wait_group %0;" :: "n"(n) : "memory")

// ---- fast transcendentals (MUFU): inputs guaranteed positive-domain ----
#define LOG2E_F 1.4426950408889634f
#define LN2_F   0.6931471805599453f
__device__ __forceinline__ float ex2_f(float x) {
    float r; asm("ex2.approx.f32 %0, %1;" : "=f"(r) : "f"(x)); return r;
}
__device__ __forceinline__ float lg2_f(float x) {
    float r; asm("lg2.approx.f32 %0, %1;" : "=f"(r) : "f"(x)); return r;
}
// softplus for x >= 0 (GEMM output is non-negative: Alpha>=0, G>=0)
__device__ __forceinline__ float softplus_fast(float x) {
    if (x > 20.0f) return x;
    return LN2_F * lg2_f(1.0f + ex2_f(x * LOG2E_F));
}
__device__ __forceinline__ float log_fast(float x) {
    return LN2_F * lg2_f(x);
}

#if TC_PATH
#define TCGEN05_LD_X32(r, tm) \
    asm volatile( \
        "tcgen05.ld.sync.aligned.32x32b.x32.b32 " \
        "{%0, %1, %2, %3, %4, %5, %6, %7, " \
        " %8, %9, %10, %11, %12, %13, %14, %15, " \
        " %16, %17, %18, %19, %20, %21, %22, %23, " \
        " %24, %25, %26, %27, %28, %29, %30, %31}, [%32];" \
        : "=r"((r)[0]),  "=r"((r)[1]),  "=r"((r)[2]),  "=r"((r)[3]), \
          "=r"((r)[4]),  "=r"((r)[5]),  "=r"((r)[6]),  "=r"((r)[7]), \
          "=r"((r)[8]),  "=r"((r)[9]),  "=r"((r)[10]), "=r"((r)[11]), \
          "=r"((r)[12]), "=r"((r)[13]), "=r"((r)[14]), "=r"((r)[15]), \
          "=r"((r)[16]), "=r"((r)[17]), "=r"((r)[18]), "=r"((r)[19]), \
          "=r"((r)[20]), "=r"((r)[21]), "=r"((r)[22]), "=r"((r)[23]), \
          "=r"((r)[24]), "=r"((r)[25]), "=r"((r)[26]), "=r"((r)[27]), \
          "=r"((r)[28]), "=r"((r)[29]), "=r"((r)[30]), "=r"((r)[31]) \
        : "r"(tm))

__device__ __forceinline__ void mma_f16_ss(uint32_t d_tmem, uint64_t a_desc,
                                           uint64_t b_desc, uint32_t idesc, bool en) {
    uint32_t e = en ? 1u : 0u;
    asm volatile(
        "{\n\t.reg .pred p;\n\t"
        "setp.ne.u32 p, %5, 0;\n\t"
        "tcgen05.mma.cta_group::1.kind::f16 [%0], %1, %2, %3, {%4, %4, %4, %4}, p;\n\t}"
        :: "r"(d_tmem), "l"(a_desc), "l"(b_desc), "r"(idesc), "r"(0u), "r"(e)
        : "memory");
}
#endif  // TC_PATH

// idesc: F32 accum, bf16 A/B, M=128, N=128
#define GEMM_IDESC 0x8200490u

// ---------------------------------------------------------------------------
// Phase 1: per-subchunk carry + row partial sums (coalesced tile load).
// ---------------------------------------------------------------------------
#define TSTRIDE 132
#define P13_SMEM (128 * TSTRIDE * 4)

__global__ void phase1_kernel(const float* __restrict__ obs,
                              const float* __restrict__ Beta) {
    extern __shared__ float st[];
    int tid = threadIdx.x;
    int c = blockIdx.x;          // 128-wide t chunk
    int kg = blockIdx.y;

#pragma unroll
    for (int p = 0; p < 16; p++) {
        int i4 = tid + p * 256;
        int kk = i4 >> 5;
        int t4 = i4 & 31;
        float4 v = *(const float4*)(obs + (size_t)(kg * 128 + kk) * NDIM + c * 128 + t4 * 4);
        *(float4*)(st + kk * TSTRIDE + t4 * 4) = v;
    }
    __syncthreads();

    int kk = tid & 127;
    int h = tid >> 7;
    int k = kg * 128 + kk;
    float betak = Beta[k];
    float d = ex2_f(-betak * LOG2E_F);
    const float* row = st + kk * TSTRIDE + h * SUBL;

    float C = 0.0f, sum = 0.0f;
#pragma unroll 4
    for (int i = 0; i < SUBL; i++) {
        float o = row[i];
        C = d * (C + o);
        sum += o;
    }
    g_Ccar[(size_t)k * NSUB + c * 2 + h] = C;
    g_psum[(size_t)k * NSUB + c * 2 + h] = sum;
}

// ---------------------------------------------------------------------------
// Phase 2: serial scan of subchunk carries per row + Mu0.
// ---------------------------------------------------------------------------
__global__ void phase2_kernel(const float* __restrict__ Beta) {
    __shared__ float sC[NSUB];
    __shared__ float sS[NSUB];
    __shared__ float ss[NSUB];
    int k = blockIdx.x;
    int tid = threadIdx.x;
    sC[tid] = g_Ccar[(size_t)k * NSUB + tid];
    ss[tid] = g_psum[(size_t)k * NSUB + tid];
    __syncthreads();
    if (tid == 0) {
        float d = ex2_f(-Beta[k] * LOG2E_F);
        float dl = d;
#pragma unroll
        for (int q = 0; q < 6; q++) dl *= dl;   // d^64 (~0, kept for exactness)
        float S = 0.0f;
        for (int c = 0; c < NSUB; c++) {
            sS[c] = S;
            S = dl * S + sC[c];
        }
    }
    for (int off = 128; off > 0; off >>= 1) {
        __syncthreads();
        if (tid < off) ss[tid] += ss[tid + off];
    }
    __syncthreads();
    g_Scar[(size_t)k * NSUB + tid] = sS[tid];
    if (tid == 0)
        g_Mu0[k] = ss[0] / (float)(NDIM * 10) + 1e-5f;
}

// ---------------------------------------------------------------------------
// Phase 3: emit G transposed bf16 via SMEM staging (coalesced in and out).
// ---------------------------------------------------------------------------
#define P3_SMEM (P13_SMEM + 128 * 128 * 2)

__global__ void phase3_kernel(const float* __restrict__ obs,
                              const float* __restrict__ Beta) {
    extern __shared__ float st[];
    __nv_bfloat16* sg = (__nv_bfloat16*)(st + 128 * TSTRIDE);
    int tid = threadIdx.x;
    int c = blockIdx.x;
    int kg = blockIdx.y;

#pragma unroll
    for (int p = 0; p < 16; p++) {
        int i4 = tid + p * 256;
        int kk = i4 >> 5;
        int t4 = i4 & 31;
        float4 v = *(const float4*)(obs + (size_t)(kg * 128 + kk) * NDIM + c * 128 + t4 * 4);
        *(float4*)(st + kk * TSTRIDE + t4 * 4) = v;
    }
    __syncthreads();

    {
        int kk = tid & 127;
        int h = tid >> 7;
        int k = kg * 128 + kk;
        float betak = Beta[k];
        float d = ex2_f(-betak * LOG2E_F);
        float S = g_Scar[(size_t)k * NSUB + c * 2 + h];
        const float* row = st + kk * TSTRIDE + h * SUBL;
#pragma unroll 4
        for (int i = 0; i < SUBL; i++) {
            sg[(h * SUBL + i) * 128 + kk] = __float2bfloat16_rn(betak * S);
            S = d * (S + row[i]);
        }
    }
    __syncthreads();

    uint32_t* gout = (uint32_t*)(g_Gbf + (size_t)c * 128 * KDIM + kg * 128);
    const uint32_t* sg32 = (const uint32_t*)sg;
#pragma unroll
    for (int p = 0; p < 32; p++) {
        int idx = tid + p * 256;
        int t = idx >> 6;
        int k2 = idx & 63;
        gout[(size_t)t * (KDIM / 2) + k2] = sg32[t * 64 + k2];
    }
}

// ---------------------------------------------------------------------------
// Alpha -> bf16
// ---------------------------------------------------------------------------
__global__ void convA_kernel(const float* __restrict__ Alpha) {
    size_t i4 = (size_t)blockIdx.x * blockDim.x + threadIdx.x;
    float4 v = ((const float4*)Alpha)[i4];
    __nv_bfloat162 lo, hi;
    lo.x = __float2bfloat16_rn(v.x); lo.y = __float2bfloat16_rn(v.y);
    hi.x = __float2bfloat16_rn(v.z); hi.y = __float2bfloat16_rn(v.w);
    ((__nv_bfloat162*)g_Abf)[i4 * 2]     = lo;
    ((__nv_bfloat162*)g_Abf)[i4 * 2 + 1] = hi;
}

// ---------------------------------------------------------------------------
// GEMM: 128x128 tile, GK=64, 16 chunks, 3-stage cp.async pipeline, occ 2,
// fused epilogue with MUFU transcendentals + fp32 loglik accumulation.
// ---------------------------------------------------------------------------
#define GM 128
#define GN 128
#define GK 64
#define NCH (KDIM / GK)       // 16
#define STAGES 3

#define OFF_TPTR  0
#define OFF_MBAR  16          // three 8-byte mbarriers
#define STAGE_BYTES 32768                    // A 16KB + B 16KB
#define OFF_A(s)  (1024 + (s) * STAGE_BYTES)
#define OFF_B(s)  (OFF_A(s) + 16384)
#define GEMM_SMEM (1024 + STAGES * STAGE_BYTES)   // 99328 -> occ 2

#if TC_PATH
// async-load one K-chunk (A: 128x64, B: 128x64 bf16) into stage s
__device__ __forceinline__ void issue_loads(uint32_t smem_base, int s, int cn,
                                            int k0, int t0) {
    int tid = threadIdx.x;
    const __nv_bfloat16* asrc = g_Abf + (size_t)k0 * KDIM + cn * GK;
    const __nv_bfloat16* bsrc = g_Gbf + (size_t)t0 * KDIM + cn * GK;
#pragma unroll
    for (int p = 0; p < 4; p++) {
        int q = tid + p * 256;            // 0..1023
        int r = q >> 3;
        int cc = q & 7;
        uint32_t sw = SMEM_SWIZZLE_128B(r * 128 + cc * 16);
        cp_async16(smem_base + OFF_A(s) + sw, asrc + (size_t)r * KDIM + cc * 8);
        cp_async16(smem_base + OFF_B(s) + sw, bsrc + (size_t)r * KDIM + cc * 8);
    }
}
#endif

__global__ __launch_bounds__(256, 2)
void gemm_kernel(const float* __restrict__ obs,
                 float* __restrict__ out, long long out_size) {
    extern __shared__ char smem[];
    int tid = threadIdx.x;
    int t0 = blockIdx.x * GN;
    int k0 = blockIdx.y * GM;
    const long long KN = (long long)KDIM * NDIM;
    bool full_out = (out_size >= 1 + 2 * KN);
    // bases offset 4B from aligned allocation: 32-bit stores only
    float* out_lams0 = out + 1;
    float* out_lam1  = out + 1 + KN;

#if TC_PATH
    uint32_t smem_base = smem_u32(smem);
    int wid = tid >> 5;
    int lid = tid & 31;

    if (tid == 0) {
#pragma unroll
        for (int s = 0; s < STAGES; s++)
            MBARRIER_INIT(smem_base + OFF_MBAR + s * 8, 1);
    }
    if (wid == 0) {
        TCGEN05_ALLOC(smem_base + OFF_TPTR, 128);
        TCGEN05_RELINQ();
    }
    __syncthreads();
    uint32_t tmem_base;
    asm volatile("ld.shared.b32 %0, [%1];" : "=r"(tmem_base) : "r"(smem_base + OFF_TPTR));

    // prologue: preload chunks 0, 1
#pragma unroll
    for (int c = 0; c < STAGES - 1; c++) {
        issue_loads(smem_base, c, c, k0, t0);
        CP_COMMIT();
    }

    int ph[STAGES] = {0, 0, 0};
    for (int c = 0; c < NCH; c++) {
        int s = c - (c / STAGES) * STAGES;          // c % 3
        if (c == NCH - 1) { CP_WAIT(0); } else { CP_WAIT(1); }
        __syncthreads();
        FENCE_PROXY_ASYNC();
        if (wid == 0) {
            if (elect_one()) {
                uint64_t ad = MAKE_SMEM_DESC(smem_base + OFF_A(s));
                uint64_t bd = MAKE_SMEM_DESC(smem_base + OFF_B(s));
#pragma unroll
                for (int sub = 0; sub < 4; sub++)
                    mma_f16_ss(tmem_base, ad + sub * 2, bd + sub * 2, GEMM_IDESC,
                               (c > 0) || (sub > 0));
                TCGEN05_COMMIT(smem_base + OFF_MBAR + s * 8);
            }
        }
        int cn = c + STAGES - 1;
        if (cn < NCH) {
            int sn = cn - (cn / STAGES) * STAGES;
            if (c >= 1) {            // stage sn last used by chunk c-1's MMA
                mbar_wait(smem_base + OFF_MBAR + sn * 8, ph[sn]);
                ph[sn] ^= 1;
            }
            issue_loads(smem_base, sn, cn, k0, t0);
            CP_COMMIT();
        }
    }
    // drain MMAs of the last 3 chunks
#pragma unroll
    for (int c = NCH - STAGES; c < NCH; c++) {
        int s = c - (c / STAGES) * STAGES;
        mbar_wait(smem_base + OFF_MBAR + s * 8, ph[s]);
        ph[s] ^= 1;
    }
    TCGEN05_FENCE_AFTER();

    // ---- epilogue: warp w -> rows (w&3)*32+lid, cols (w>>2)*64 + half*32 ----
    int k = k0 + (wid & 3) * 32 + lid;
    int coloff = (wid >> 2) * 64;
    float mu = g_Mu0[k];
    float lsum = 0.0f;    // fp32: 64 terms per thread, well within tolerance

#pragma unroll
    for (int half = 0; half < 2; half++) {
        uint32_t dr[32];
        TCGEN05_LD_X32(dr, tmem_base + coloff + half * 32);
        TCGEN05_WAIT_LD();
        int tb = t0 + coloff + half * 32;
        const float* orow = obs + (size_t)k * NDIM + tb;
        float* l1row = out_lam1 + (size_t)k * NDIM + tb;
        float* l0row = out_lams0 + (size_t)k * NDIM + tb;
#pragma unroll
        for (int j = 0; j < 32; j += 4) {
            float4 o = *(const float4*)(orow + j);
            float4 l1;
            l1.x = softplus_fast(__uint_as_float(dr[j]));
            l1.y = softplus_fast(__uint_as_float(dr[j + 1]));
            l1.z = softplus_fast(__uint_as_float(dr[j + 2]));
            l1.w = softplus_fast(__uint_as_float(dr[j + 3]));
            if (tb + j == 0) l1.x = 0.0f;   // t == 0 branch
            if (full_out) {
                l1row[j]     = l1.x;
                l1row[j + 1] = l1.y;
                l1row[j + 2] = l1.z;
                l1row[j + 3] = l1.w;
                l0row[j]     = mu;
                l0row[j + 1] = mu;
                l0row[j + 2] = mu;
                l0row[j + 3] = mu;
            }
            lsum += o.x * log_fast(mu + l1.x + 1e-5f) - l1.x;
            lsum += o.y * log_fast(mu + l1.y + 1e-5f) - l1.y;
            lsum += o.z * log_fast(mu + l1.z + 1e-5f) - l1.z;
            lsum += o.w * log_fast(mu + l1.w + 1e-5f) - l1.w;
        }
    }
    lsum -= 64.0f * mu;   // hoisted -mu per element (64 elems/thread)
    TCGEN05_FENCE_BEFORE();

    double* dred = (double*)(smem + OFF_A(0));
    __syncthreads();
    dred[tid] = (double)lsum;
    __syncthreads();
    for (int off = 128; off > 0; off >>= 1) {
        if (tid < off) dred[tid] += dred[tid + off];
        __syncthreads();
    }
    if (tid == 0)
        g_partials[blockIdx.y * gridDim.x + blockIdx.x] = dred[0];

    if (tid == 0) {
#pragma unroll
        for (int s = 0; s < STAGES; s++)
            MBARRIER_INVAL(smem_base + OFF_MBAR + s * 8);
    }
    __syncthreads();
    if (wid == 0)
        TCGEN05_DEALLOC(tmem_base, 128);

#else  // ---------------- SIMT fallback (non-'a' PTX pass; never runs on bench GPU)
    int tx = tid & 15;
    int ty = tid >> 4;
    float acc[8][8];
#pragma unroll
    for (int i = 0; i < 8; i++)
#pragma unroll
        for (int j = 0; j < 8; j++) acc[i][j] = 0.0f;

    for (int jj = 0; jj < KDIM; jj++) {
        float a[8], b[8];
#pragma unroll
        for (int i = 0; i < 8; i++)
            a[i] = __bfloat162float(g_Abf[(size_t)(k0 + ty * 8 + i) * KDIM + jj]);
#pragma unroll
        for (int j = 0; j < 8; j++)
            b[j] = __bfloat162float(g_Gbf[(size_t)(t0 + tx * 8 + j) * KDIM + jj]);
#pragma unroll
        for (int i = 0; i < 8; i++)
#pragma unroll
            for (int j = 0; j < 8; j++) acc[i][j] = fmaf(a[i], b[j], acc[i][j]);
    }

    float lsum = 0.0f;
#pragma unroll
    for (int i = 0; i < 8; i++) {
        int k = k0 + ty * 8 + i;
        float mu = g_Mu0[k];
#pragma unroll
        for (int j = 0; j < 8; j++) {
            int t = t0 + tx * 8 + j;
            float lam = softplus_fast(acc[i][j] > 0.0f ? acc[i][j] : 0.0f);
            if (t == 0) lam = 0.0f;
            size_t idx = (size_t)k * NDIM + t;
            if (full_out) {
                out_lams0[idx] = mu;
                out_lam1[idx]  = lam;
            }
            float o = obs[idx];
            lsum += o * log_fast(mu + lam + 1e-5f) - mu - lam;
        }
    }
    double* dred = (double*)smem;
    dred[tid] = (double)lsum;
    __syncthreads();
    for (int off = 128; off > 0; off >>= 1) {
        if (tid < off) dred[tid] += dred[tid + off];
        __syncthreads();
    }
    if (tid == 0)
        g_partials[blockIdx.y * gridDim.x + blockIdx.x] = dred[0];
#endif
}

// ---------------------------------------------------------------------------
// Final reduction of 1024 double partials -> out[0]
// ---------------------------------------------------------------------------
__global__ void final_reduce_kernel(float* __restrict__ out) {
    __shared__ double dred[256];
    int tid = threadIdx.x;
    double s = 0.0;
    for (int i = tid; i < 1024; i += 256) s += g_partials[i];
    dred[tid] = s;
    __syncthreads();
    for (int off = 128; off > 0; off >>= 1) {
        if (tid < off) dred[tid] += dred[tid + off];
        __syncthreads();
    }
    if (tid == 0) out[0] = (float)dred[0];
}

// ---------------------------------------------------------------------------
extern "C" void kernel_launch(void* const* d_in, const int* in_sizes, int n_in,
                              void* d_out, int out_size) {
    const float* obs   = (const float*)d_in[0];   // [K, N]
    const float* Beta  = (const float*)d_in[1];   // [K]
    const float* Alpha = (const float*)d_in[2];   // [K, K]
    float* out = (float*)d_out;

    cudaFuncSetAttribute(gemm_kernel,
                         cudaFuncAttributeMaxDynamicSharedMemorySize, GEMM_SMEM);
    cudaFuncSetAttribute(phase1_kernel,
                         cudaFuncAttributeMaxDynamicSharedMemorySize, P13_SMEM);
    cudaFuncSetAttribute(phase3_kernel,
                         cudaFuncAttributeMaxDynamicSharedMemorySize, P3_SMEM);

    phase1_kernel<<<dim3(NDIM / 128, KDIM / 128), 256, P13_SMEM>>>(obs, Beta);
    convA_kernel<<<KDIM, 256>>>(Alpha);
    phase2_kernel<<<KDIM, NSUB>>>(Beta);
    phase3_kernel<<<dim3(NDIM / 128, KDIM / 128), 256, P3_SMEM>>>(obs, Beta);

    dim3 grid(NDIM / GN, KDIM / GM);   // (128, 8)
    gemm_kernel<<<grid, 256, GEMM_SMEM>>>(obs, out, (long long)out_size);

    final_reduce_kernel<<<1, 256>>>(out);
}

// round 9
// speedup vs baseline: 2.5649x; 1.7761x over previous
#include <cuda_runtime.h>
#include <cuda_bf16.h>
#include <math.h>
#include <stdint.h>

#define KDIM 1024
#define NDIM 16384
#define SUBL 64                   // sub-chunk length for the scan
#define NSUB (NDIM / SUBL)        // 256 sub-chunks per row

// Feature gate: tcgen05 only exists on the sm_103a ('a'-feature) compile pass.
#if defined(__CUDA_ARCH_FEAT_SM103_ALL)
#define TC_PATH 1
#else
#define TC_PATH 0
#endif

// ---------------------------------------------------------------------------
// Scratch (device globals: allocation-free rule)
// ---------------------------------------------------------------------------
__device__ __align__(1024) __nv_bfloat16 g_Abf[(size_t)KDIM * KDIM]; // Alpha bf16 [k][j]
__device__ __align__(1024) __nv_bfloat16 g_Gbf[(size_t)NDIM * KDIM]; // G bf16 [t][j]
__device__ float  g_Ccar[(size_t)KDIM * NSUB];   // per-subchunk carry
__device__ float  g_psum[(size_t)KDIM * NSUB];   // per-subchunk row-sum
__device__ float  g_Scar[(size_t)KDIM * NSUB];   // subchunk-start S values
__device__ float  g_Mu0[KDIM];
__device__ double g_partials[1024];

// ---------------------------------------------------------------------------
// PTX helpers (sm_103a)
// ---------------------------------------------------------------------------
__device__ __forceinline__ uint32_t smem_u32(const void* p) {
    uint32_t a;
    asm("{ .reg .u64 t; cvta.to.shared.u64 t, %1; cvt.u32.u64 %0, t; }" : "=r"(a) : "l"(p));
    return a;
}
__device__ __forceinline__ uint32_t elect_one() {
    uint32_t p;
    asm volatile("{\n\t.reg .pred p;\n\telect.sync _|p, 0xFFFFFFFF;\n\tselp.b32 %0, 1, 0, p;\n\t}" : "=r"(p));
    return p;
}
#define SMEM_SWIZZLE_128B(x) ((x) ^ (((x) >> 3) & 0x70))

static __device__ constexpr uint64_t SMEM_DESC_BASE_SW128 =
    (uint64_t(2) << 61) | (uint64_t(1) << 46) | (uint64_t(64) << 32) | (uint64_t(1) << 16);
#define MAKE_SMEM_DESC(a) (SMEM_DESC_BASE_SW128 | ((uint64_t)((a) >> 4) & 0x3FFF))

#define TCGEN05_ALLOC(sm, n) \
    asm volatile("tcgen05.alloc.cta_group::1.sync.aligned.shared::cta.b32 [%0], %1;" :: "r"((uint32_t)(sm)), "r"((uint32_t)(n)) : "memory")
#define TCGEN05_DEALLOC(tm, n) \
    asm volatile("tcgen05.dealloc.cta_group::1.sync.aligned.b32 %0, %1;" :: "r"(tm), "r"((uint32_t)(n)))
#define TCGEN05_RELINQ() \
    asm volatile("tcgen05.relinquish_alloc_permit.cta_group::1.sync.aligned;")
#define TCGEN05_COMMIT(mb) \
    asm volatile("tcgen05.commit.cta_group::1.mbarrier::arrive::one.shared::cluster.b64 [%0];" :: "r"((uint32_t)(mb)) : "memory")
#define TCGEN05_WAIT_LD()  asm volatile("tcgen05.wait::ld.sync.aligned;" ::: "memory")
#define TCGEN05_FENCE_AFTER() asm volatile("tcgen05.fence::after_thread_sync;" ::: "memory")
#define TCGEN05_FENCE_BEFORE() asm volatile("tcgen05.fence::before_thread_sync;" ::: "memory")
#define FENCE_PROXY_ASYNC() asm volatile("fence.proxy.async.shared::cta;" ::: "memory")
#define MBARRIER_INIT(mb, c) \
    asm volatile("mbarrier.init.shared.b64 [%0], %1;" :: "r"((uint32_t)(mb)), "r"((uint32_t)(c)) : "memory")
#define MBARRIER_INVAL(mb) \
    asm volatile("mbarrier.inval.shared.b64 [%0];" :: "r"((uint32_t)(mb)) : "memory")

__device__ __forceinline__ void mbar_wait(uint32_t addr, uint32_t parity) {
    asm volatile(
        "{\n\t.reg .pred P;\n\t"
        "LW%=:\n\t"
        "mbarrier.try_wait.parity.acquire.cta.shared::cta.b64 P, [%0], %1, 0x989680;\n\t"
        "@!P bra LW%=;\n\t}"
        :: "r"(addr), "r"(parity) : "memory");
}

__device__ __forceinline__ void cp_async16(uint32_t dst, const void* src) {
    asm volatile("cp.async.cg.shared.global [%0], [%1], 16;" :: "r"(dst), "l"(src));
}
#define CP_COMMIT() asm volatile("cp.async.commit_group;" ::: "memory")
#define CP_WAIT(n)  asm volatile("cp.async.wait_group %0;" :: "n"(n) : "memory")

// ---- fast transcendentals (MUFU): inputs guaranteed positive-domain ----
#define LOG2E_F 1.4426950408889634f
#define LN2_F   0.6931471805599453f
__device__ __forceinline__ float ex2_f(float x) {
    float r; asm("ex2.approx.f32 %0, %1;" : "=f"(r) : "f"(x)); return r;
}
__device__ __forceinline__ float lg2_f(float x) {
    float r; asm("lg2.approx.f32 %0, %1;" : "=f"(r) : "f"(x)); return r;
}
// softplus for x >= 0 (GEMM output is non-negative: Alpha>=0, G>=0)
__device__ __forceinline__ float softplus_fast(float x) {
    if (x > 20.0f) return x;
    return LN2_F * lg2_f(1.0f + ex2_f(x * LOG2E_F));
}
__device__ __forceinline__ float log_fast(float x) {
    return LN2_F * lg2_f(x);
}

#if TC_PATH
#define TCGEN05_LD_X32(r, tm) \
    asm volatile( \
        "tcgen05.ld.sync.aligned.32x32b.x32.b32 " \
        "{%0, %1, %2, %3, %4, %5, %6, %7, " \
        " %8, %9, %10, %11, %12, %13, %14, %15, " \
        " %16, %17, %18, %19, %20, %21, %22, %23, " \
        " %24, %25, %26, %27, %28, %29, %30, %31}, [%32];" \
        : "=r"((r)[0]),  "=r"((r)[1]),  "=r"((r)[2]),  "=r"((r)[3]), \
          "=r"((r)[4]),  "=r"((r)[5]),  "=r"((r)[6]),  "=r"((r)[7]), \
          "=r"((r)[8]),  "=r"((r)[9]),  "=r"((r)[10]), "=r"((r)[11]), \
          "=r"((r)[12]), "=r"((r)[13]), "=r"((r)[14]), "=r"((r)[15]), \
          "=r"((r)[16]), "=r"((r)[17]), "=r"((r)[18]), "=r"((r)[19]), \
          "=r"((r)[20]), "=r"((r)[21]), "=r"((r)[22]), "=r"((r)[23]), \
          "=r"((r)[24]), "=r"((r)[25]), "=r"((r)[26]), "=r"((r)[27]), \
          "=r"((r)[28]), "=r"((r)[29]), "=r"((r)[30]), "=r"((r)[31]) \
        : "r"(tm))

__device__ __forceinline__ void mma_f16_ss(uint32_t d_tmem, uint64_t a_desc,
                                           uint64_t b_desc, uint32_t idesc, bool en) {
    uint32_t e = en ? 1u : 0u;
    asm volatile(
        "{\n\t.reg .pred p;\n\t"
        "setp.ne.u32 p, %5, 0;\n\t"
        "tcgen05.mma.cta_group::1.kind::f16 [%0], %1, %2, %3, {%4, %4, %4, %4}, p;\n\t}"
        :: "r"(d_tmem), "l"(a_desc), "l"(b_desc), "r"(idesc), "r"(0u), "r"(e)
        : "memory");
}
#endif  // TC_PATH

// idesc: F32 accum, bf16 A/B, M=128, N=128
#define GEMM_IDESC 0x8200490u

// ---------------------------------------------------------------------------
// Phase 1: per-subchunk carry + row partial sums (coalesced tile load).
// ---------------------------------------------------------------------------
#define TSTRIDE 132
#define P13_SMEM (128 * TSTRIDE * 4)

__global__ void phase1_kernel(const float* __restrict__ obs,
                              const float* __restrict__ Beta) {
    extern __shared__ float st[];
    int tid = threadIdx.x;
    int c = blockIdx.x;          // 128-wide t chunk
    int kg = blockIdx.y;

#pragma unroll
    for (int p = 0; p < 16; p++) {
        int i4 = tid + p * 256;
        int kk = i4 >> 5;
        int t4 = i4 & 31;
        float4 v = *(const float4*)(obs + (size_t)(kg * 128 + kk) * NDIM + c * 128 + t4 * 4);
        *(float4*)(st + kk * TSTRIDE + t4 * 4) = v;
    }
    __syncthreads();

    int kk = tid & 127;
    int h = tid >> 7;
    int k = kg * 128 + kk;
    float betak = Beta[k];
    float d = ex2_f(-betak * LOG2E_F);
    const float* row = st + kk * TSTRIDE + h * SUBL;

    float C = 0.0f, sum = 0.0f;
#pragma unroll 4
    for (int i = 0; i < SUBL; i++) {
        float o = row[i];
        C = d * (C + o);
        sum += o;
    }
    g_Ccar[(size_t)k * NSUB + c * 2 + h] = C;
    g_psum[(size_t)k * NSUB + c * 2 + h] = sum;
}

// ---------------------------------------------------------------------------
// Phase 2: serial scan of subchunk carries per row + Mu0.
// ---------------------------------------------------------------------------
__global__ void phase2_kernel(const float* __restrict__ Beta) {
    __shared__ float sC[NSUB];
    __shared__ float sS[NSUB];
    __shared__ float ss[NSUB];
    int k = blockIdx.x;
    int tid = threadIdx.x;
    sC[tid] = g_Ccar[(size_t)k * NSUB + tid];
    ss[tid] = g_psum[(size_t)k * NSUB + tid];
    __syncthreads();
    if (tid == 0) {
        float d = ex2_f(-Beta[k] * LOG2E_F);
        float dl = d;
#pragma unroll
        for (int q = 0; q < 6; q++) dl *= dl;   // d^64 (~0, kept for exactness)
        float S = 0.0f;
        for (int c = 0; c < NSUB; c++) {
            sS[c] = S;
            S = dl * S + sC[c];
        }
    }
    for (int off = 128; off > 0; off >>= 1) {
        __syncthreads();
        if (tid < off) ss[tid] += ss[tid + off];
    }
    __syncthreads();
    g_Scar[(size_t)k * NSUB + tid] = sS[tid];
    if (tid == 0)
        g_Mu0[k] = ss[0] / (float)(NDIM * 10) + 1e-5f;
}

// ---------------------------------------------------------------------------
// Phase 3: emit G transposed bf16 via SMEM staging (coalesced in and out).
// ---------------------------------------------------------------------------
#define P3_SMEM (P13_SMEM + 128 * 128 * 2)

__global__ void phase3_kernel(const float* __restrict__ obs,
                              const float* __restrict__ Beta) {
    extern __shared__ float st[];
    __nv_bfloat16* sg = (__nv_bfloat16*)(st + 128 * TSTRIDE);
    int tid = threadIdx.x;
    int c = blockIdx.x;
    int kg = blockIdx.y;

#pragma unroll
    for (int p = 0; p < 16; p++) {
        int i4 = tid + p * 256;
        int kk = i4 >> 5;
        int t4 = i4 & 31;
        float4 v = *(const float4*)(obs + (size_t)(kg * 128 + kk) * NDIM + c * 128 + t4 * 4);
        *(float4*)(st + kk * TSTRIDE + t4 * 4) = v;
    }
    __syncthreads();

    {
        int kk = tid & 127;
        int h = tid >> 7;
        int k = kg * 128 + kk;
        float betak = Beta[k];
        float d = ex2_f(-betak * LOG2E_F);
        float S = g_Scar[(size_t)k * NSUB + c * 2 + h];
        const float* row = st + kk * TSTRIDE + h * SUBL;
#pragma unroll 4
        for (int i = 0; i < SUBL; i++) {
            sg[(h * SUBL + i) * 128 + kk] = __float2bfloat16_rn(betak * S);
            S = d * (S + row[i]);
        }
    }
    __syncthreads();

    uint32_t* gout = (uint32_t*)(g_Gbf + (size_t)c * 128 * KDIM + kg * 128);
    const uint32_t* sg32 = (const uint32_t*)sg;
#pragma unroll
    for (int p = 0; p < 32; p++) {
        int idx = tid + p * 256;
        int t = idx >> 6;
        int k2 = idx & 63;
        gout[(size_t)t * (KDIM / 2) + k2] = sg32[t * 64 + k2];
    }
}

// ---------------------------------------------------------------------------
// Alpha -> bf16
// ---------------------------------------------------------------------------
__global__ void convA_kernel(const float* __restrict__ Alpha) {
    size_t i4 = (size_t)blockIdx.x * blockDim.x + threadIdx.x;
    float4 v = ((const float4*)Alpha)[i4];
    __nv_bfloat162 lo, hi;
    lo.x = __float2bfloat16_rn(v.x); lo.y = __float2bfloat16_rn(v.y);
    hi.x = __float2bfloat16_rn(v.z); hi.y = __float2bfloat16_rn(v.w);
    ((__nv_bfloat162*)g_Abf)[i4 * 2]     = lo;
    ((__nv_bfloat162*)g_Abf)[i4 * 2 + 1] = hi;
}

// ---------------------------------------------------------------------------
// GEMM: 128x128 tile, GK=64, 16 chunks, 3-stage cp.async pipeline, occ 2,
// epilogue transposed through SMEM so all global accesses are coalesced.
// ---------------------------------------------------------------------------
#define GM 128
#define GN 128
#define GK 64
#define NCH (KDIM / GK)       // 16
#define STAGES 3

#define OFF_TPTR  0
#define OFF_MBAR  16          // three 8-byte mbarriers
#define STAGE_BYTES 32768                    // A 16KB + B 16KB
#define OFF_A(s)  (1024 + (s) * STAGE_BYTES)
#define OFF_B(s)  (OFF_A(s) + 16384)
#define GEMM_SMEM (1024 + STAGES * STAGE_BYTES)   // 99328 -> occ 2
#define EPI_STRIDE 129        // f32 staging stride (odd -> conflict-free k-stores)

#if TC_PATH
// async-load one K-chunk (A: 128x64, B: 128x64 bf16) into stage s
__device__ __forceinline__ void issue_loads(uint32_t smem_base, int s, int cn,
                                            int k0, int t0) {
    int tid = threadIdx.x;
    const __nv_bfloat16* asrc = g_Abf + (size_t)k0 * KDIM + cn * GK;
    const __nv_bfloat16* bsrc = g_Gbf + (size_t)t0 * KDIM + cn * GK;
#pragma unroll
    for (int p = 0; p < 4; p++) {
        int q = tid + p * 256;            // 0..1023
        int r = q >> 3;
        int cc = q & 7;
        uint32_t sw = SMEM_SWIZZLE_128B(r * 128 + cc * 16);
        cp_async16(smem_base + OFF_A(s) + sw, asrc + (size_t)r * KDIM + cc * 8);
        cp_async16(smem_base + OFF_B(s) + sw, bsrc + (size_t)r * KDIM + cc * 8);
    }
}
#endif

__global__ __launch_bounds__(256, 2)
void gemm_kernel(const float* __restrict__ obs,
                 float* __restrict__ out, long long out_size) {
    extern __shared__ char smem[];
    int tid = threadIdx.x;
    int t0 = blockIdx.x * GN;
    int k0 = blockIdx.y * GM;
    const long long KN = (long long)KDIM * NDIM;
    bool full_out = (out_size >= 1 + 2 * KN);
    // bases offset 4B from aligned allocation: 32-bit stores only
    float* out_lams0 = out + 1;
    float* out_lam1  = out + 1 + KN;

#if TC_PATH
    uint32_t smem_base = smem_u32(smem);
    int wid = tid >> 5;
    int lid = tid & 31;

    if (tid == 0) {
#pragma unroll
        for (int s = 0; s < STAGES; s++)
            MBARRIER_INIT(smem_base + OFF_MBAR + s * 8, 1);
    }
    if (wid == 0) {
        TCGEN05_ALLOC(smem_base + OFF_TPTR, 128);
        TCGEN05_RELINQ();
    }
    __syncthreads();
    uint32_t tmem_base;
    asm volatile("ld.shared.b32 %0, [%1];" : "=r"(tmem_base) : "r"(smem_base + OFF_TPTR));

    // prologue: preload chunks 0, 1
#pragma unroll
    for (int c = 0; c < STAGES - 1; c++) {
        issue_loads(smem_base, c, c, k0, t0);
        CP_COMMIT();
    }

    int ph[STAGES] = {0, 0, 0};
    for (int c = 0; c < NCH; c++) {
        int s = c - (c / STAGES) * STAGES;          // c % 3
        if (c == NCH - 1) { CP_WAIT(0); } else { CP_WAIT(1); }
        __syncthreads();
        FENCE_PROXY_ASYNC();
        if (wid == 0) {
            if (elect_one()) {
                uint64_t ad = MAKE_SMEM_DESC(smem_base + OFF_A(s));
                uint64_t bd = MAKE_SMEM_DESC(smem_base + OFF_B(s));
#pragma unroll
                for (int sub = 0; sub < 4; sub++)
                    mma_f16_ss(tmem_base, ad + sub * 2, bd + sub * 2, GEMM_IDESC,
                               (c > 0) || (sub > 0));
                TCGEN05_COMMIT(smem_base + OFF_MBAR + s * 8);
            }
        }
        int cn = c + STAGES - 1;
        if (cn < NCH) {
            int sn = cn - (cn / STAGES) * STAGES;
            if (c >= 1) {            // stage sn last used by chunk c-1's MMA
                mbar_wait(smem_base + OFF_MBAR + sn * 8, ph[sn]);
                ph[sn] ^= 1;
            }
            issue_loads(smem_base, sn, cn, k0, t0);
            CP_COMMIT();
        }
    }
    // drain MMAs of the last 3 chunks
#pragma unroll
    for (int c = NCH - STAGES; c < NCH; c++) {
        int s = c - (c / STAGES) * STAGES;
        mbar_wait(smem_base + OFF_MBAR + s * 8, ph[s]);
        ph[s] ^= 1;
    }
    TCGEN05_FENCE_AFTER();

    // ---- epilogue stage 1: TMEM -> SMEM f32 tile [128k][128t], stride 129 ----
    float* sg = (float*)(smem + 1024);   // 128*129*4 = 66048 B, fits in dead buffers
    {
        int r = (wid & 3) * 32 + lid;
        int coloff = (wid >> 2) * 64;
#pragma unroll
        for (int half = 0; half < 2; half++) {
            uint32_t dr[32];
            TCGEN05_LD_X32(dr, tmem_base + coloff + half * 32);
            TCGEN05_WAIT_LD();
            float* dstp = sg + r * EPI_STRIDE + coloff + half * 32;
#pragma unroll
            for (int j = 0; j < 32; j++) dstp[j] = __uint_as_float(dr[j]);
        }
    }
    TCGEN05_FENCE_BEFORE();
    __syncthreads();

    // ---- epilogue stage 2: t-major coalesced writeout + loglik ----
    float lsum = 0.0f;
#pragma unroll 4
    for (int p = 0; p < 64; p++) {
        int flat = p * 256 + tid;
        int kl = flat >> 7;           // 0..127
        int tl = flat & 127;          // lanes cover consecutive t
        int kg = k0 + kl;
        int tg = t0 + tl;
        float mu = g_Mu0[kg];
        float x = sg[kl * EPI_STRIDE + tl];
        float l1 = softplus_fast(x);
        if (tg == 0) l1 = 0.0f;       // t == 0 branch
        size_t idx = (size_t)kg * NDIM + tg;
        if (full_out) {
            out_lam1[idx]  = l1;      // coalesced 128B/warp
            out_lams0[idx] = mu;
        }
        float o = obs[idx];           // coalesced
        lsum += o * log_fast(mu + l1 + 1e-5f) - mu - l1;
    }
    __syncthreads();

    double* dred = (double*)(smem + 1024);
    dred[tid] = (double)lsum;
    __syncthreads();
    for (int off = 128; off > 0; off >>= 1) {
        if (tid < off) dred[tid] += dred[tid + off];
        __syncthreads();
    }
    if (tid == 0)
        g_partials[blockIdx.y * gridDim.x + blockIdx.x] = dred[0];

    if (tid == 0) {
#pragma unroll
        for (int s = 0; s < STAGES; s++)
            MBARRIER_INVAL(smem_base + OFF_MBAR + s * 8);
    }
    __syncthreads();
    if (wid == 0)
        TCGEN05_DEALLOC(tmem_base, 128);

#else  // ---------------- SIMT fallback (non-'a' PTX pass; never runs on bench GPU)
    int tx = tid & 15;
    int ty = tid >> 4;
    float acc[8][8];
#pragma unroll
    for (int i = 0; i < 8; i++)
#pragma unroll
        for (int j = 0; j < 8; j++) acc[i][j] = 0.0f;

    for (int jj = 0; jj < KDIM; jj++) {
        float a[8], b[8];
#pragma unroll
        for (int i = 0; i < 8; i++)
            a[i] = __bfloat162float(g_Abf[(size_t)(k0 + ty * 8 + i) * KDIM + jj]);
#pragma unroll
        for (int j = 0; j < 8; j++)
            b[j] = __bfloat162float(g_Gbf[(size_t)(t0 + tx * 8 + j) * KDIM + jj]);
#pragma unroll
        for (int i = 0; i < 8; i++)
#pragma unroll
            for (int j = 0; j < 8; j++) acc[i][j] = fmaf(a[i], b[j], acc[i][j]);
    }

    float lsum = 0.0f;
#pragma unroll
    for (int i = 0; i < 8; i++) {
        int k = k0 + ty * 8 + i;
        float mu = g_Mu0[k];
#pragma unroll
        for (int j = 0; j < 8; j++) {
            int t = t0 + tx * 8 + j;
            float lam = softplus_fast(acc[i][j] > 0.0f ? acc[i][j] : 0.0f);
            if (t == 0) lam = 0.0f;
            size_t idx = (size_t)k * NDIM + t;
            if (full_out) {
                out_lams0[idx] = mu;
                out_lam1[idx]  = lam;
            }
            float o = obs[idx];
            lsum += o * log_fast(mu + lam + 1e-5f) - mu - lam;
        }
    }
    double* dred = (double*)smem;
    dred[tid] = (double)lsum;
    __syncthreads();
    for (int off = 128; off > 0; off >>= 1) {
        if (tid < off) dred[tid] += dred[tid + off];
        __syncthreads();
    }
    if (tid == 0)
        g_partials[blockIdx.y * gridDim.x + blockIdx.x] = dred[0];
#endif
}

// ---------------------------------------------------------------------------
// Final reduction of 1024 double partials -> out[0]
// ---------------------------------------------------------------------------
__global__ void final_reduce_kernel(float* __restrict__ out) {
    __shared__ double dred[256];
    int tid = threadIdx.x;
    double s = 0.0;
    for (int i = tid; i < 1024; i += 256) s += g_partials[i];
    dred[tid] = s;
    __syncthreads();
    for (int off = 128; off > 0; off >>= 1) {
        if (tid < off) dred[tid] += dred[tid + off];
        __syncthreads();
    }
    if (tid == 0) out[0] = (float)dred[0];
}

// ---------------------------------------------------------------------------
extern "C" void kernel_launch(void* const* d_in, const int* in_sizes, int n_in,
                              void* d_out, int out_size) {
    const float* obs   = (const float*)d_in[0];   // [K, N]
    const float* Beta  = (const float*)d_in[1];   // [K]
    const float* Alpha = (const float*)d_in[2];   // [K, K]
    float* out = (float*)d_out;

    cudaFuncSetAttribute(gemm_kernel,
                         cudaFuncAttributeMaxDynamicSharedMemorySize, GEMM_SMEM);
    cudaFuncSetAttribute(phase1_kernel,
                         cudaFuncAttributeMaxDynamicSharedMemorySize, P13_SMEM);
    cudaFuncSetAttribute(phase3_kernel,
                         cudaFuncAttributeMaxDynamicSharedMemorySize, P3_SMEM);

    phase1_kernel<<<dim3(NDIM / 128, KDIM / 128), 256, P13_SMEM>>>(obs, Beta);
    convA_kernel<<<KDIM, 256>>>(Alpha);
    phase2_kernel<<<KDIM, NSUB>>>(Beta);
    phase3_kernel<<<dim3(NDIM / 128, KDIM / 128), 256, P3_SMEM>>>(obs, Beta);

    dim3 grid(NDIM / GN, KDIM / GM);   // (128, 8)
    gemm_kernel<<<grid, 256, GEMM_SMEM>>>(obs, out, (long long)out_size);

    final_reduce_kernel<<<1, 256>>>(out);
}

// round 11
// speedup vs baseline: 2.7993x; 1.0914x over previous
#include <cuda_runtime.h>
#include <cuda_bf16.h>
#include <math.h>
#include <stdint.h>

#define KDIM 1024
#define NDIM 16384
#define SUBL 64                   // sub-chunk length for the scan
#define NSUB (NDIM / SUBL)        // 256 sub-chunks per row

// Feature gate: tcgen05 only exists on the sm_103a ('a'-feature) compile pass.
#if defined(__CUDA_ARCH_FEAT_SM103_ALL)
#define TC_PATH 1
#else
#define TC_PATH 0
#endif

// ---------------------------------------------------------------------------
// Scratch (device globals: allocation-free rule)
// ---------------------------------------------------------------------------
__device__ __align__(1024) __nv_bfloat16 g_Abf[(size_t)KDIM * KDIM]; // Alpha bf16 [k][j]
__device__ __align__(1024) __nv_bfloat16 g_Gbf[(size_t)NDIM * KDIM]; // G bf16 [t][j]
__device__ float  g_Ccar[(size_t)KDIM * NSUB];   // per-subchunk carry
__device__ float  g_psum[(size_t)KDIM * NSUB];   // per-subchunk row-sum
__device__ float  g_Scar[(size_t)KDIM * NSUB];   // subchunk-start S values
__device__ float  g_Mu0[KDIM];
__device__ double g_partials[512];

// ---------------------------------------------------------------------------
// PTX helpers (sm_103a)
// ---------------------------------------------------------------------------
__device__ __forceinline__ uint32_t smem_u32(const void* p) {
    uint32_t a;
    asm("{ .reg .u64 t; cvta.to.shared.u64 t, %1; cvt.u32.u64 %0, t; }" : "=r"(a) : "l"(p));
    return a;
}
__device__ __forceinline__ uint32_t elect_one() {
    uint32_t p;
    asm volatile("{\n\t.reg .pred p;\n\telect.sync _|p, 0xFFFFFFFF;\n\tselp.b32 %0, 1, 0, p;\n\t}" : "=r"(p));
    return p;
}
#define SMEM_SWIZZLE_128B(x) ((x) ^ (((x) >> 3) & 0x70))

static __device__ constexpr uint64_t SMEM_DESC_BASE_SW128 =
    (uint64_t(2) << 61) | (uint64_t(1) << 46) | (uint64_t(64) << 32) | (uint64_t(1) << 16);
#define MAKE_SMEM_DESC(a) (SMEM_DESC_BASE_SW128 | ((uint64_t)((a) >> 4) & 0x3FFF))

#define TCGEN05_ALLOC(sm, n) \
    asm volatile("tcgen05.alloc.cta_group::1.sync.aligned.shared::cta.b32 [%0], %1;" :: "r"((uint32_t)(sm)), "r"((uint32_t)(n)) : "memory")
#define TCGEN05_DEALLOC(tm, n) \
    asm volatile("tcgen05.dealloc.cta_group::1.sync.aligned.b32 %0, %1;" :: "r"(tm), "r"((uint32_t)(n)))
#define TCGEN05_RELINQ() \
    asm volatile("tcgen05.relinquish_alloc_permit.cta_group::1.sync.aligned;")
#define TCGEN05_COMMIT(mb) \
    asm volatile("tcgen05.commit.cta_group::1.mbarrier::arrive::one.shared::cluster.b64 [%0];" :: "r"((uint32_t)(mb)) : "memory")
#define TCGEN05_WAIT_LD()  asm volatile("tcgen05.wait::ld.sync.aligned;" ::: "memory")
#define TCGEN05_FENCE_AFTER() asm volatile("tcgen05.fence::after_thread_sync;" ::: "memory")
#define TCGEN05_FENCE_BEFORE() asm volatile("tcgen05.fence::before_thread_sync;" ::: "memory")
#define FENCE_PROXY_ASYNC() asm volatile("fence.proxy.async.shared::cta;" ::: "memory")
#define MBARRIER_INIT(mb, c) \
    asm volatile("mbarrier.init.shared.b64 [%0], %1;" :: "r"((uint32_t)(mb)), "r"((uint32_t)(c)) : "memory")
#define MBARRIER_INVAL(mb) \
    asm volatile("mbarrier.inval.shared.b64 [%0];" :: "r"((uint32_t)(mb)) : "memory")

__device__ __forceinline__ void mbar_wait(uint32_t addr, uint32_t parity) {
    asm volatile(
        "{\n\t.reg .pred P;\n\t"
        "LW%=:\n\t"
        "mbarrier.try_wait.parity.acquire.cta.shared::cta.b64 P, [%0], %1, 0x989680;\n\t"
        "@!P bra LW%=;\n\t}"
        :: "r"(addr), "r"(parity) : "memory");
}

__device__ __forceinline__ void cp_async16(uint32_t dst, const void* src) {
    asm volatile("cp.async.cg.shared.global [%0], [%1], 16;" :: "r"(dst), "l"(src));
}
#define CP_COMMIT() asm volatile("cp.async.commit_group;" ::: "memory")
#define CP_WAIT(n)  asm volatile("cp.async.wait_group %0;" :: "n"(n) : "memory")

// ---- fast transcendentals (MUFU): inputs guaranteed positive-domain ----
#define LOG2E_F 1.4426950408889634f
#define LN2_F   0.6931471805599453f
__device__ __forceinline__ float ex2_f(float x) {
    float r; asm("ex2.approx.f32 %0, %1;" : "=f"(r) : "f"(x)); return r;
}
__device__ __forceinline__ float lg2_f(float x) {
    float r; asm("lg2.approx.f32 %0, %1;" : "=f"(r) : "f"(x)); return r;
}
// softplus for x >= 0 (GEMM output is non-negative: Alpha>=0, G>=0)
__device__ __forceinline__ float softplus_fast(float x) {
    if (x > 20.0f) return x;
    return LN2_F * lg2_f(1.0f + ex2_f(x * LOG2E_F));
}
__device__ __forceinline__ float log_fast(float x) {
    return LN2_F * lg2_f(x);
}

#if TC_PATH
#define TCGEN05_LD_X32(r, tm) \
    asm volatile( \
        "tcgen05.ld.sync.aligned.32x32b.x32.b32 " \
        "{%0, %1, %2, %3, %4, %5, %6, %7, " \
        " %8, %9, %10, %11, %12, %13, %14, %15, " \
        " %16, %17, %18, %19, %20, %21, %22, %23, " \
        " %24, %25, %26, %27, %28, %29, %30, %31}, [%32];" \
        : "=r"((r)[0]),  "=r"((r)[1]),  "=r"((r)[2]),  "=r"((r)[3]), \
          "=r"((r)[4]),  "=r"((r)[5]),  "=r"((r)[6]),  "=r"((r)[7]), \
          "=r"((r)[8]),  "=r"((r)[9]),  "=r"((r)[10]), "=r"((r)[11]), \
          "=r"((r)[12]), "=r"((r)[13]), "=r"((r)[14]), "=r"((r)[15]), \
          "=r"((r)[16]), "=r"((r)[17]), "=r"((r)[18]), "=r"((r)[19]), \
          "=r"((r)[20]), "=r"((r)[21]), "=r"((r)[22]), "=r"((r)[23]), \
          "=r"((r)[24]), "=r"((r)[25]), "=r"((r)[26]), "=r"((r)[27]), \
          "=r"((r)[28]), "=r"((r)[29]), "=r"((r)[30]), "=r"((r)[31]) \
        : "r"(tm))

__device__ __forceinline__ void mma_f16_ss(uint32_t d_tmem, uint64_t a_desc,
                                           uint64_t b_desc, uint32_t idesc, bool en) {
    uint32_t e = en ? 1u : 0u;
    asm volatile(
        "{\n\t.reg .pred p;\n\t"
        "setp.ne.u32 p, %5, 0;\n\t"
        "tcgen05.mma.cta_group::1.kind::f16 [%0], %1, %2, %3, {%4, %4, %4, %4}, p;\n\t}"
        :: "r"(d_tmem), "l"(a_desc), "l"(b_desc), "r"(idesc), "r"(0u), "r"(e)
        : "memory");
}
#endif  // TC_PATH

// idesc: F32 accum, bf16 A/B, M=128, N=256
#define GEMM_IDESC 0x8400490u

// ---------------------------------------------------------------------------
// Phase 1: per-subchunk carry + row partial sums (coalesced tile load).
// TSTRIDE must be a multiple of 4 (float4-aligned rows). 132 proven.
// ---------------------------------------------------------------------------
#define TSTRIDE 132
#define P13_SMEM (128 * TSTRIDE * 4)

__global__ void phase1_kernel(const float* __restrict__ obs,
                              const float* __restrict__ Beta) {
    extern __shared__ float st[];
    int tid = threadIdx.x;
    int c = blockIdx.x;          // 128-wide t chunk
    int kg = blockIdx.y;

#pragma unroll
    for (int p = 0; p < 16; p++) {
        int i4 = tid + p * 256;
        int kk = i4 >> 5;
        int t4 = i4 & 31;
        float4 v = *(const float4*)(obs + (size_t)(kg * 128 + kk) * NDIM + c * 128 + t4 * 4);
        *(float4*)(st + kk * TSTRIDE + t4 * 4) = v;
    }
    __syncthreads();

    int kk = tid & 127;
    int h = tid >> 7;
    int k = kg * 128 + kk;
    float betak = Beta[k];
    float d = ex2_f(-betak * LOG2E_F);
    const float* row = st + kk * TSTRIDE + h * SUBL;

    float C = 0.0f, sum = 0.0f;
#pragma unroll 4
    for (int i = 0; i < SUBL; i++) {
        float o = row[i];
        C = d * (C + o);
        sum += o;
    }
    g_Ccar[(size_t)k * NSUB + c * 2 + h] = C;
    g_psum[(size_t)k * NSUB + c * 2 + h] = sum;
}

// ---------------------------------------------------------------------------
// Phase 2: serial scan of subchunk carries per row + Mu0.
// ---------------------------------------------------------------------------
__global__ void phase2_kernel(const float* __restrict__ Beta) {
    __shared__ float sC[NSUB];
    __shared__ float sS[NSUB];
    __shared__ float ss[NSUB];
    int k = blockIdx.x;
    int tid = threadIdx.x;
    sC[tid] = g_Ccar[(size_t)k * NSUB + tid];
    ss[tid] = g_psum[(size_t)k * NSUB + tid];
    __syncthreads();
    if (tid == 0) {
        float d = ex2_f(-Beta[k] * LOG2E_F);
        float dl = d;
#pragma unroll
        for (int q = 0; q < 6; q++) dl *= dl;   // d^64 (~0, kept for exactness)
        float S = 0.0f;
        for (int c = 0; c < NSUB; c++) {
            sS[c] = S;
            S = dl * S + sC[c];
        }
    }
    for (int off = 128; off > 0; off >>= 1) {
        __syncthreads();
        if (tid < off) ss[tid] += ss[tid + off];
    }
    __syncthreads();
    g_Scar[(size_t)k * NSUB + tid] = sS[tid];
    if (tid == 0)
        g_Mu0[k] = ss[0] / (float)(NDIM * 10) + 1e-5f;
}

// ---------------------------------------------------------------------------
// Phase 3: emit G transposed bf16 via SMEM staging (coalesced in and out).
// ---------------------------------------------------------------------------
#define P3_SMEM (P13_SMEM + 128 * 128 * 2)

__global__ void phase3_kernel(const float* __restrict__ obs,
                              const float* __restrict__ Beta) {
    extern __shared__ float st[];
    __nv_bfloat16* sg = (__nv_bfloat16*)(st + 128 * TSTRIDE);
    int tid = threadIdx.x;
    int c = blockIdx.x;
    int kg = blockIdx.y;

#pragma unroll
    for (int p = 0; p < 16; p++) {
        int i4 = tid + p * 256;
        int kk = i4 >> 5;
        int t4 = i4 & 31;
        float4 v = *(const float4*)(obs + (size_t)(kg * 128 + kk) * NDIM + c * 128 + t4 * 4);
        *(float4*)(st + kk * TSTRIDE + t4 * 4) = v;
    }
    __syncthreads();

    {
        int kk = tid & 127;
        int h = tid >> 7;
        int k = kg * 128 + kk;
        float betak = Beta[k];
        float d = ex2_f(-betak * LOG2E_F);
        float S = g_Scar[(size_t)k * NSUB + c * 2 + h];
        const float* row = st + kk * TSTRIDE + h * SUBL;
#pragma unroll 4
        for (int i = 0; i < SUBL; i++) {
            sg[(h * SUBL + i) * 128 + kk] = __float2bfloat16_rn(betak * S);
            S = d * (S + row[i]);
        }
    }
    __syncthreads();

    uint32_t* gout = (uint32_t*)(g_Gbf + (size_t)c * 128 * KDIM + kg * 128);
    const uint32_t* sg32 = (const uint32_t*)sg;
#pragma unroll
    for (int p = 0; p < 32; p++) {
        int idx = tid + p * 256;
        int t = idx >> 6;
        int k2 = idx & 63;
        gout[(size_t)t * (KDIM / 2) + k2] = sg32[t * 64 + k2];
    }
}

// ---------------------------------------------------------------------------
// Alpha -> bf16
// ---------------------------------------------------------------------------
__global__ void convA_kernel(const float* __restrict__ Alpha) {
    size_t i4 = (size_t)blockIdx.x * blockDim.x + threadIdx.x;
    float4 v = ((const float4*)Alpha)[i4];
    __nv_bfloat162 lo, hi;
    lo.x = __float2bfloat16_rn(v.x); lo.y = __float2bfloat16_rn(v.y);
    hi.x = __float2bfloat16_rn(v.z); hi.y = __float2bfloat16_rn(v.w);
    ((__nv_bfloat162*)g_Abf)[i4 * 2]     = lo;
    ((__nv_bfloat162*)g_Abf)[i4 * 2 + 1] = hi;
}

// ---------------------------------------------------------------------------
// GEMM: 128(M=k) x 256(N=t) tile, GK=64, 16 chunks, 2-stage cp.async pipeline,
// occ 2. Epilogue in two 128-col halves, transposed through SMEM (coalesced).
// ---------------------------------------------------------------------------
#define GM 128
#define GN 256
#define GK 64
#define NCH (KDIM / GK)       // 16
#define STAGES 2

#define OFF_TPTR  0
#define OFF_MBAR  16          // two 8-byte mbarriers
#define STAGE_BYTES (16384 + 32768)          // A 16KB + B 32KB
#define OFF_A(s)  (1024 + (s) * STAGE_BYTES)
#define OFF_B(s)  (OFF_A(s) + 16384)
#define GEMM_SMEM (1024 + STAGES * STAGE_BYTES)   // 99328 -> occ 2
#define EPI_STRIDE 129        // f32 staging stride (odd -> conflict-free k-stores)

#if TC_PATH
// async-load one K-chunk (A: 128x64, B: 256x64 bf16) into stage s
__device__ __forceinline__ void issue_loads(uint32_t smem_base, int s, int cn,
                                            int k0, int t0) {
    int tid = threadIdx.x;
    const __nv_bfloat16* asrc = g_Abf + (size_t)k0 * KDIM + cn * GK;
    const __nv_bfloat16* bsrc = g_Gbf + (size_t)t0 * KDIM + cn * GK;
#pragma unroll
    for (int p = 0; p < 4; p++) {
        int q = tid + p * 256;            // 0..1023
        int r = q >> 3;
        int cc = q & 7;
        uint32_t sw = SMEM_SWIZZLE_128B(r * 128 + cc * 16);
        cp_async16(smem_base + OFF_A(s) + sw, asrc + (size_t)r * KDIM + cc * 8);
    }
#pragma unroll
    for (int p = 0; p < 8; p++) {
        int q = tid + p * 256;            // 0..2047
        int r = q >> 3;                   // 0..255
        int cc = q & 7;
        uint32_t sw = SMEM_SWIZZLE_128B(r * 128 + cc * 16);
        cp_async16(smem_base + OFF_B(s) + sw, bsrc + (size_t)r * KDIM + cc * 8);
    }
}
#endif

__global__ __launch_bounds__(256, 2)
void gemm_kernel(const float* __restrict__ obs,
                 float* __restrict__ out, long long out_size) {
    extern __shared__ char smem[];
    int tid = threadIdx.x;
    int t0 = blockIdx.x * GN;
    int k0 = blockIdx.y * GM;
    const long long KN = (long long)KDIM * NDIM;
    bool full_out = (out_size >= 1 + 2 * KN);
    // bases offset 4B from aligned allocation: 32-bit stores only
    float* out_lams0 = out + 1;
    float* out_lam1  = out + 1 + KN;

#if TC_PATH
    uint32_t smem_base = smem_u32(smem);
    int wid = tid >> 5;
    int lid = tid & 31;

    if (tid == 0) {
        MBARRIER_INIT(smem_base + OFF_MBAR, 1);
        MBARRIER_INIT(smem_base + OFF_MBAR + 8, 1);
    }
    if (wid == 0) {
        TCGEN05_ALLOC(smem_base + OFF_TPTR, 256);
        TCGEN05_RELINQ();
    }
    __syncthreads();
    uint32_t tmem_base;
    asm volatile("ld.shared.b32 %0, [%1];" : "=r"(tmem_base) : "r"(smem_base + OFF_TPTR));

    // prologue: preload chunk 0 into stage 0
    issue_loads(smem_base, 0, 0, k0, t0);
    CP_COMMIT();

    int ph[2] = {0, 0};
    for (int c = 0; c < NCH; c++) {
        int s = c & 1;
        // prefetch next chunk into the other buffer (after its MMA drained)
        if (c + 1 < NCH) {
            int sn = s ^ 1;
            if (c >= 1) {      // buffer sn last used by chunk c-1's MMA
                mbar_wait(smem_base + OFF_MBAR + sn * 8, ph[sn]);
                ph[sn] ^= 1;
            }
            issue_loads(smem_base, sn, c + 1, k0, t0);
            CP_COMMIT();
            CP_WAIT(1);        // chunk c's loads complete (c+1 may be pending)
        } else {
            CP_WAIT(0);
        }
        __syncthreads();
        FENCE_PROXY_ASYNC();
        if (wid == 0) {
            if (elect_one()) {
                uint64_t ad = MAKE_SMEM_DESC(smem_base + OFF_A(s));
                uint64_t bd = MAKE_SMEM_DESC(smem_base + OFF_B(s));
#pragma unroll
                for (int sub = 0; sub < 4; sub++)
                    mma_f16_ss(tmem_base, ad + sub * 2, bd + sub * 2, GEMM_IDESC,
                               (c > 0) || (sub > 0));
                TCGEN05_COMMIT(smem_base + OFF_MBAR + s * 8);
            }
        }
    }
    // drain: chunks 14 (mbar0) and 15 (mbar1)
    mbar_wait(smem_base + OFF_MBAR, ph[0]);
    mbar_wait(smem_base + OFF_MBAR + 8, ph[1]);
    TCGEN05_FENCE_AFTER();

    // ---- epilogue: two 128-col halves, each staged via SMEM then coalesced ----
    float* sg = (float*)(smem + 1024);   // 128*129*4 = 66048 B (dead buffers)
    float lsum = 0.0f;
    int sp = wid & 3;                    // TMEM subpartition (row group)
    int cg = wid >> 2;                   // column sub-group within half

#pragma unroll
    for (int hh = 0; hh < 2; hh++) {
        // TMEM -> SMEM (rows = k, cols = t within half)
#pragma unroll
        for (int q = 0; q < 2; q++) {
            uint32_t dr[32];
            TCGEN05_LD_X32(dr, tmem_base + hh * 128 + cg * 64 + q * 32);
            TCGEN05_WAIT_LD();
            float* dstp = sg + (sp * 32 + lid) * EPI_STRIDE + cg * 64 + q * 32;
#pragma unroll
            for (int j = 0; j < 32; j++) dstp[j] = __uint_as_float(dr[j]);
        }
        __syncthreads();

        // t-major coalesced writeout + loglik
#pragma unroll 4
        for (int p = 0; p < 64; p++) {
            int flat = p * 256 + tid;
            int kl = flat >> 7;           // 0..127
            int tl = flat & 127;          // lanes cover consecutive t
            int kg = k0 + kl;
            int tg = t0 + hh * 128 + tl;
            float mu = g_Mu0[kg];
            float x = sg[kl * EPI_STRIDE + tl];
            float l1 = softplus_fast(x);
            if (tg == 0) l1 = 0.0f;       // t == 0 branch
            size_t idx = (size_t)kg * NDIM + tg;
            if (full_out) {
                out_lam1[idx]  = l1;      // coalesced 128B/warp
                out_lams0[idx] = mu;
            }
            float o = obs[idx];           // coalesced
            lsum += o * log_fast(mu + l1 + 1e-5f) - mu - l1;
        }
        __syncthreads();
    }
    TCGEN05_FENCE_BEFORE();

    double* dred = (double*)(smem + 1024);
    dred[tid] = (double)lsum;
    __syncthreads();
    for (int off = 128; off > 0; off >>= 1) {
        if (tid < off) dred[tid] += dred[tid + off];
        __syncthreads();
    }
    if (tid == 0)
        g_partials[blockIdx.y * gridDim.x + blockIdx.x] = dred[0];

    if (tid == 0) {
        MBARRIER_INVAL(smem_base + OFF_MBAR);
        MBARRIER_INVAL(smem_base + OFF_MBAR + 8);
    }
    __syncthreads();
    if (wid == 0)
        TCGEN05_DEALLOC(tmem_base, 256);

#else  // ---------------- SIMT fallback (non-'a' PTX pass; never runs on bench GPU)
    int tx = tid & 15;
    int ty = tid >> 4;
    float acc[8][16];
#pragma unroll
    for (int i = 0; i < 8; i++)
#pragma unroll
        for (int j = 0; j < 16; j++) acc[i][j] = 0.0f;

    for (int jj = 0; jj < KDIM; jj++) {
        float a[8], b[16];
#pragma unroll
        for (int i = 0; i < 8; i++)
            a[i] = __bfloat162float(g_Abf[(size_t)(k0 + ty * 8 + i) * KDIM + jj]);
#pragma unroll
        for (int j = 0; j < 16; j++)
            b[j] = __bfloat162float(g_Gbf[(size_t)(t0 + tx * 16 + j) * KDIM + jj]);
#pragma unroll
        for (int i = 0; i < 8; i++)
#pragma unroll
            for (int j = 0; j < 16; j++) acc[i][j] = fmaf(a[i], b[j], acc[i][j]);
    }

    float lsum = 0.0f;
#pragma unroll
    for (int i = 0; i < 8; i++) {
        int k = k0 + ty * 8 + i;
        float mu = g_Mu0[k];
#pragma unroll
        for (int j = 0; j < 16; j++) {
            int t = t0 + tx * 16 + j;
            float lam = softplus_fast(acc[i][j] > 0.0f ? acc[i][j] : 0.0f);
            if (t == 0) lam = 0.0f;
            size_t idx = (size_t)k * NDIM + t;
            if (full_out) {
                out_lams0[idx] = mu;
                out_lam1[idx]  = lam;
            }
            float o = obs[idx];
            lsum += o * log_fast(mu + lam + 1e-5f) - mu - lam;
        }
    }
    double* dred = (double*)smem;
    dred[tid] = (double)lsum;
    __syncthreads();
    for (int off = 128; off > 0; off >>= 1) {
        if (tid < off) dred[tid] += dred[tid + off];
        __syncthreads();
    }
    if (tid == 0)
        g_partials[blockIdx.y * gridDim.x + blockIdx.x] = dred[0];
#endif
}

// ---------------------------------------------------------------------------
// Final reduction of 512 double partials -> out[0]
// ---------------------------------------------------------------------------
__global__ void final_reduce_kernel(float* __restrict__ out) {
    __shared__ double dred[256];
    int tid = threadIdx.x;
    double s = 0.0;
    for (int i = tid; i < 512; i += 256) s += g_partials[i];
    dred[tid] = s;
    __syncthreads();
    for (int off = 128; off > 0; off >>= 1) {
        if (tid < off) dred[tid] += dred[tid + off];
        __syncthreads();
    }
    if (tid == 0) out[0] = (float)dred[0];
}

// ---------------------------------------------------------------------------
extern "C" void kernel_launch(void* const* d_in, const int* in_sizes, int n_in,
                              void* d_out, int out_size) {
    const float* obs   = (const float*)d_in[0];   // [K, N]
    const float* Beta  = (const float*)d_in[1];   // [K]
    const float* Alpha = (const float*)d_in[2];   // [K, K]
    float* out = (float*)d_out;

    cudaFuncSetAttribute(gemm_kernel,
                         cudaFuncAttributeMaxDynamicSharedMemorySize, GEMM_SMEM);
    cudaFuncSetAttribute(phase1_kernel,
                         cudaFuncAttributeMaxDynamicSharedMemorySize, P13_SMEM);
    cudaFuncSetAttribute(phase3_kernel,
                         cudaFuncAttributeMaxDynamicSharedMemorySize, P3_SMEM);

    phase1_kernel<<<dim3(NDIM / 128, KDIM / 128), 256, P13_SMEM>>>(obs, Beta);
    convA_kernel<<<KDIM, 256>>>(Alpha);
    phase2_kernel<<<KDIM, NSUB>>>(Beta);
    phase3_kernel<<<dim3(NDIM / 128, KDIM / 128), 256, P3_SMEM>>>(obs, Beta);

    dim3 grid(NDIM / GN, KDIM / GM);   // (64, 8)
    gemm_kernel<<<grid, 256, GEMM_SMEM>>>(obs, out, (long long)out_size);

    final_reduce_kernel<<<1, 256>>>(out);
}

// round 12
// speedup vs baseline: 3.0448x; 1.0877x over previous
#include <cuda_runtime.h>
#include <cuda_bf16.h>
#include <math.h>
#include <stdint.h>

#define KDIM 1024
#define NDIM 16384

// Feature gate: tcgen05 only exists on the sm_103a ('a'-feature) compile pass.
#if defined(__CUDA_ARCH_FEAT_SM103_ALL)
#define TC_PATH 1
#else
#define TC_PATH 0
#endif

// ---------------------------------------------------------------------------
// Scratch (device globals: allocation-free rule)
// ---------------------------------------------------------------------------
__device__ __align__(1024) __nv_bfloat16 g_Abf[(size_t)KDIM * KDIM]; // Alpha bf16 [k][j]
__device__ __align__(1024) __nv_bfloat16 g_Gbf[(size_t)NDIM * KDIM]; // G bf16 [t][j]
__device__ float  g_psum[(size_t)KDIM * 128];    // per-(row, t-chunk) partial sum
__device__ float  g_Mu0[KDIM];
__device__ double g_partials[512];

// ---------------------------------------------------------------------------
// PTX helpers (sm_103a)
// ---------------------------------------------------------------------------
__device__ __forceinline__ uint32_t smem_u32(const void* p) {
    uint32_t a;
    asm("{ .reg .u64 t; cvta.to.shared.u64 t, %1; cvt.u32.u64 %0, t; }" : "=r"(a) : "l"(p));
    return a;
}
__device__ __forceinline__ uint32_t elect_one() {
    uint32_t p;
    asm volatile("{\n\t.reg .pred p;\n\telect.sync _|p, 0xFFFFFFFF;\n\tselp.b32 %0, 1, 0, p;\n\t}" : "=r"(p));
    return p;
}
#define SMEM_SWIZZLE_128B(x) ((x) ^ (((x) >> 3) & 0x70))

static __device__ constexpr uint64_t SMEM_DESC_BASE_SW128 =
    (uint64_t(2) << 61) | (uint64_t(1) << 46) | (uint64_t(64) << 32) | (uint64_t(1) << 16);
#define MAKE_SMEM_DESC(a) (SMEM_DESC_BASE_SW128 | ((uint64_t)((a) >> 4) & 0x3FFF))

#define TCGEN05_ALLOC(sm, n) \
    asm volatile("tcgen05.alloc.cta_group::1.sync.aligned.shared::cta.b32 [%0], %1;" :: "r"((uint32_t)(sm)), "r"((uint32_t)(n)) : "memory")
#define TCGEN05_DEALLOC(tm, n) \
    asm volatile("tcgen05.dealloc.cta_group::1.sync.aligned.b32 %0, %1;" :: "r"(tm), "r"((uint32_t)(n)))
#define TCGEN05_RELINQ() \
    asm volatile("tcgen05.relinquish_alloc_permit.cta_group::1.sync.aligned;")
#define TCGEN05_COMMIT(mb) \
    asm volatile("tcgen05.commit.cta_group::1.mbarrier::arrive::one.shared::cluster.b64 [%0];" :: "r"((uint32_t)(mb)) : "memory")
#define TCGEN05_WAIT_LD()  asm volatile("tcgen05.wait::ld.sync.aligned;" ::: "memory")
#define TCGEN05_FENCE_AFTER() asm volatile("tcgen05.fence::after_thread_sync;" ::: "memory")
#define TCGEN05_FENCE_BEFORE() asm volatile("tcgen05.fence::before_thread_sync;" ::: "memory")
#define FENCE_PROXY_ASYNC() asm volatile("fence.proxy.async.shared::cta;" ::: "memory")
#define MBARRIER_INIT(mb, c) \
    asm volatile("mbarrier.init.shared.b64 [%0], %1;" :: "r"((uint32_t)(mb)), "r"((uint32_t)(c)) : "memory")
#define MBARRIER_INVAL(mb) \
    asm volatile("mbarrier.inval.shared.b64 [%0];" :: "r"((uint32_t)(mb)) : "memory")

__device__ __forceinline__ void mbar_wait(uint32_t addr, uint32_t parity) {
    asm volatile(
        "{\n\t.reg .pred P;\n\t"
        "LW%=:\n\t"
        "mbarrier.try_wait.parity.acquire.cta.shared::cta.b64 P, [%0], %1, 0x989680;\n\t"
        "@!P bra LW%=;\n\t}"
        :: "r"(addr), "r"(parity) : "memory");
}

__device__ __forceinline__ void cp_async16(uint32_t dst, const void* src) {
    asm volatile("cp.async.cg.shared.global [%0], [%1], 16;" :: "r"(dst), "l"(src));
}
#define CP_COMMIT() asm volatile("cp.async.commit_group;" ::: "memory")
#define CP_WAIT(n)  asm volatile("cp.async.wait_group %0;" :: "n"(n) : "memory")

// ---- fast transcendentals (MUFU): inputs guaranteed positive-domain ----
#define LOG2E_F 1.4426950408889634f
#define LN2_F   0.6931471805599453f
__device__ __forceinline__ float ex2_f(float x) {
    float r; asm("ex2.approx.f32 %0, %1;" : "=f"(r) : "f"(x)); return r;
}
__device__ __forceinline__ float lg2_f(float x) {
    float r; asm("lg2.approx.f32 %0, %1;" : "=f"(r) : "f"(x)); return r;
}
// softplus for x >= 0 (GEMM output is non-negative: Alpha>=0, G>=0)
__device__ __forceinline__ float softplus_fast(float x) {
    if (x > 20.0f) return x;
    return LN2_F * lg2_f(1.0f + ex2_f(x * LOG2E_F));
}
__device__ __forceinline__ float log_fast(float x) {
    return LN2_F * lg2_f(x);
}

#if TC_PATH
#define TCGEN05_LD_X32(r, tm) \
    asm volatile( \
        "tcgen05.ld.sync.aligned.32x32b.x32.b32 " \
        "{%0, %1, %2, %3, %4, %5, %6, %7, " \
        " %8, %9, %10, %11, %12, %13, %14, %15, " \
        " %16, %17, %18, %19, %20, %21, %22, %23, " \
        " %24, %25, %26, %27, %28, %29, %30, %31}, [%32];" \
        : "=r"((r)[0]),  "=r"((r)[1]),  "=r"((r)[2]),  "=r"((r)[3]), \
          "=r"((r)[4]),  "=r"((r)[5]),  "=r"((r)[6]),  "=r"((r)[7]), \
          "=r"((r)[8]),  "=r"((r)[9]),  "=r"((r)[10]), "=r"((r)[11]), \
          "=r"((r)[12]), "=r"((r)[13]), "=r"((r)[14]), "=r"((r)[15]), \
          "=r"((r)[16]), "=r"((r)[17]), "=r"((r)[18]), "=r"((r)[19]), \
          "=r"((r)[20]), "=r"((r)[21]), "=r"((r)[22]), "=r"((r)[23]), \
          "=r"((r)[24]), "=r"((r)[25]), "=r"((r)[26]), "=r"((r)[27]), \
          "=r"((r)[28]), "=r"((r)[29]), "=r"((r)[30]), "=r"((r)[31]) \
        : "r"(tm))

__device__ __forceinline__ void mma_f16_ss(uint32_t d_tmem, uint64_t a_desc,
                                           uint64_t b_desc, uint32_t idesc, bool en) {
    uint32_t e = en ? 1u : 0u;
    asm volatile(
        "{\n\t.reg .pred p;\n\t"
        "setp.ne.u32 p, %5, 0;\n\t"
        "tcgen05.mma.cta_group::1.kind::f16 [%0], %1, %2, %3, {%4, %4, %4, %4}, p;\n\t}"
        :: "r"(d_tmem), "l"(a_desc), "l"(b_desc), "r"(idesc), "r"(0u), "r"(e)
        : "memory");
}
#endif  // TC_PATH

// idesc: F32 accum, bf16 A/B, M=128, N=256
#define GEMM_IDESC 0x8400490u

// ---------------------------------------------------------------------------
// Fused scan kernel: grid (128 t-chunks, 8 k-groups), 256 threads (8 warps).
// Key facts: d^128 = exp(-128*Beta) == 0 in fp32 (Beta >= 1), so the chunk-
// start state S_start[c] equals the carry of chunk c-1 computed locally.
// Each warp handles one row at a time (16 rows):
//   1. coalesced float4 load of PREVIOUS chunk; per-lane affine map (a=d^4,b);
//      ordered tree reduce (offs 1,2,4,8,16 keep segments adjacent) -> S0.
//   2. coalesced load of CURRENT chunk; Hillis-Steele inclusive affine scan,
//      shift to exclusive -> per-lane starting S; emit 4 G = Beta*S values
//      into a rotation-swizzled SMEM tile (conflict-free STS).
//   3. warp-reduce row sum -> g_psum (Mu0).
// Then one coalesced block writeout of the bf16 [t][k] tile.
// ---------------------------------------------------------------------------
__global__ void scan_fused_kernel(const float* __restrict__ obs,
                                  const float* __restrict__ Beta) {
    __shared__ uint32_t sg[128 * 64];   // 32 KB: [t 0..127][kpair 0..63] bf16x2
    int tid = threadIdx.x;
    int wid = tid >> 5;
    int lid = tid & 31;
    int c = blockIdx.x;          // 128-wide t chunk
    int kg = blockIdx.y;

    for (int p = 0; p < 16; p++) {
        int kk = wid * 16 + p;           // local row 0..127
        int row = kg * 128 + kk;
        float beta = Beta[row];
        float d = ex2_f(-beta * LOG2E_F);
        float d2 = d * d, d4 = d2 * d2;
        const float* rbase = obs + (size_t)row * NDIM;

        // --- previous-chunk carry -> S0 (S_start of chunk c) ---
        float S0 = 0.0f;
        if (c > 0) {
            float4 po = *(const float4*)(rbase + (c - 1) * 128 + lid * 4);
            float a = d4;
            float b = d * po.x;
            b = d * (b + po.y);
            b = d * (b + po.z);
            b = d * (b + po.w);
            // ordered tree reduce: ascending offsets keep ranges adjacent;
            // lane 0 ends with the full-chunk composition.
#pragma unroll
            for (int off = 1; off < 32; off <<= 1) {
                float aR = __shfl_down_sync(0xffffffffu, a, off);
                float bR = __shfl_down_sync(0xffffffffu, b, off);
                b = b * aR + bR;     // earlier(self) then later(received)
                a = a * aR;
            }
            S0 = __shfl_sync(0xffffffffu, b, 0);  // a_total*S_prev ~ 1e-56 -> dropped
        }

        // --- current chunk: per-lane local affine + row-sum term ---
        float4 o = *(const float4*)(rbase + c * 128 + lid * 4);
        float ia = d4;
        float ib = d * o.x;
        ib = d * (ib + o.y);
        ib = d * (ib + o.z);
        ib = d * (ib + o.w);
        float suml = o.x + o.y + o.z + o.w;

        // inclusive affine scan over lanes (Hillis-Steele, ordered)
#pragma unroll
        for (int off = 1; off < 32; off <<= 1) {
            float pa = __shfl_up_sync(0xffffffffu, ia, off);
            float pb = __shfl_up_sync(0xffffffffu, ib, off);
            if (lid >= off) {
                ib = pb * ia + ib;   // prev(received) then cur(self)
                ia = pa * ia;
            }
        }
        // exclusive: lane l gets composition of lanes 0..l-1
        float ea = __shfl_up_sync(0xffffffffu, ia, 1);
        float eb = __shfl_up_sync(0xffffffffu, ib, 1);
        if (lid == 0) { ea = 1.0f; eb = 0.0f; }
        float S = ea * S0 + eb;      // S at t = c*128 + 4*lid

        // --- emit 4 G values into swizzled SMEM tile ---
        int kpair = kk >> 1, klow = kk & 1;
        char* sgb = (char*)sg;
#pragma unroll
        for (int i = 0; i < 4; i++) {
            int t = 4 * lid + i;
            int colp = (kpair + lid) & 63;   // rotation swizzle (t>>2 == lid)
            *(__nv_bfloat16*)(sgb + t * 256 + colp * 4 + klow * 2) =
                __float2bfloat16_rn(beta * S);
            float oi = (i == 0) ? o.x : (i == 1) ? o.y : (i == 2) ? o.z : o.w;
            S = d * (S + oi);
        }

        // --- row partial sum for Mu0 ---
#pragma unroll
        for (int off = 16; off > 0; off >>= 1)
            suml += __shfl_down_sync(0xffffffffu, suml, off);
        if (lid == 0)
            g_psum[(size_t)row * 128 + c] = suml;
    }
    __syncthreads();

    // --- coalesced writeout (u32 = bf16x2), undoing the rotation swizzle ---
    uint32_t* gout = (uint32_t*)(g_Gbf + (size_t)c * 128 * KDIM + kg * 128);
#pragma unroll
    for (int p = 0; p < 32; p++) {
        int idx = tid + p * 256;
        int t = idx >> 6;
        int k2 = idx & 63;
        gout[(size_t)t * (KDIM / 2) + k2] = sg[t * 64 + ((k2 + (t >> 2)) & 63)];
    }
}

// ---------------------------------------------------------------------------
// Mu0 finalize: reduce 128 chunk sums per row.
// ---------------------------------------------------------------------------
__global__ void mu0_kernel() {
    __shared__ float ss[128];
    int k = blockIdx.x;
    int tid = threadIdx.x;
    ss[tid] = g_psum[(size_t)k * 128 + tid];
    __syncthreads();
    for (int off = 64; off > 0; off >>= 1) {
        if (tid < off) ss[tid] += ss[tid + off];
        __syncthreads();
    }
    if (tid == 0)
        g_Mu0[k] = ss[0] / (float)(NDIM * 10) + 1e-5f;
}

// ---------------------------------------------------------------------------
// Alpha -> bf16
// ---------------------------------------------------------------------------
__global__ void convA_kernel(const float* __restrict__ Alpha) {
    size_t i4 = (size_t)blockIdx.x * blockDim.x + threadIdx.x;
    float4 v = ((const float4*)Alpha)[i4];
    __nv_bfloat162 lo, hi;
    lo.x = __float2bfloat16_rn(v.x); lo.y = __float2bfloat16_rn(v.y);
    hi.x = __float2bfloat16_rn(v.z); hi.y = __float2bfloat16_rn(v.w);
    ((__nv_bfloat162*)g_Abf)[i4 * 2]     = lo;
    ((__nv_bfloat162*)g_Abf)[i4 * 2 + 1] = hi;
}

// ---------------------------------------------------------------------------
// GEMM: 128(M=k) x 256(N=t) tile, GK=64, 16 chunks, 2-stage cp.async pipeline,
// occ 2. Epilogue in two 128-col halves, transposed through SMEM (coalesced).
// ---------------------------------------------------------------------------
#define GM 128
#define GN 256
#define GK 64
#define NCH (KDIM / GK)       // 16
#define STAGES 2

#define OFF_TPTR  0
#define OFF_MBAR  16          // two 8-byte mbarriers
#define STAGE_BYTES (16384 + 32768)          // A 16KB + B 32KB
#define OFF_A(s)  (1024 + (s) * STAGE_BYTES)
#define OFF_B(s)  (OFF_A(s) + 16384)
#define GEMM_SMEM (1024 + STAGES * STAGE_BYTES)   // 99328 -> occ 2
#define EPI_STRIDE 129        // f32 staging stride (odd -> conflict-free k-stores)

#if TC_PATH
// async-load one K-chunk (A: 128x64, B: 256x64 bf16) into stage s
__device__ __forceinline__ void issue_loads(uint32_t smem_base, int s, int cn,
                                            int k0, int t0) {
    int tid = threadIdx.x;
    const __nv_bfloat16* asrc = g_Abf + (size_t)k0 * KDIM + cn * GK;
    const __nv_bfloat16* bsrc = g_Gbf + (size_t)t0 * KDIM + cn * GK;
#pragma unroll
    for (int p = 0; p < 4; p++) {
        int q = tid + p * 256;            // 0..1023
        int r = q >> 3;
        int cc = q & 7;
        uint32_t sw = SMEM_SWIZZLE_128B(r * 128 + cc * 16);
        cp_async16(smem_base + OFF_A(s) + sw, asrc + (size_t)r * KDIM + cc * 8);
    }
#pragma unroll
    for (int p = 0; p < 8; p++) {
        int q = tid + p * 256;            // 0..2047
        int r = q >> 3;                   // 0..255
        int cc = q & 7;
        uint32_t sw = SMEM_SWIZZLE_128B(r * 128 + cc * 16);
        cp_async16(smem_base + OFF_B(s) + sw, bsrc + (size_t)r * KDIM + cc * 8);
    }
}
#endif

__global__ __launch_bounds__(256, 2)
void gemm_kernel(const float* __restrict__ obs,
                 float* __restrict__ out, long long out_size) {
    extern __shared__ char smem[];
    int tid = threadIdx.x;
    int t0 = blockIdx.x * GN;
    int k0 = blockIdx.y * GM;
    const long long KN = (long long)KDIM * NDIM;
    bool full_out = (out_size >= 1 + 2 * KN);
    // bases offset 4B from aligned allocation: 32-bit stores only
    float* out_lams0 = out + 1;
    float* out_lam1  = out + 1 + KN;

#if TC_PATH
    uint32_t smem_base = smem_u32(smem);
    int wid = tid >> 5;
    int lid = tid & 31;

    if (tid == 0) {
        MBARRIER_INIT(smem_base + OFF_MBAR, 1);
        MBARRIER_INIT(smem_base + OFF_MBAR + 8, 1);
    }
    if (wid == 0) {
        TCGEN05_ALLOC(smem_base + OFF_TPTR, 256);
        TCGEN05_RELINQ();
    }
    __syncthreads();
    uint32_t tmem_base;
    asm volatile("ld.shared.b32 %0, [%1];" : "=r"(tmem_base) : "r"(smem_base + OFF_TPTR));

    // prologue: preload chunk 0 into stage 0
    issue_loads(smem_base, 0, 0, k0, t0);
    CP_COMMIT();

    int ph[2] = {0, 0};
    for (int c = 0; c < NCH; c++) {
        int s = c & 1;
        // prefetch next chunk into the other buffer (after its MMA drained)
        if (c + 1 < NCH) {
            int sn = s ^ 1;
            if (c >= 1) {      // buffer sn last used by chunk c-1's MMA
                mbar_wait(smem_base + OFF_MBAR + sn * 8, ph[sn]);
                ph[sn] ^= 1;
            }
            issue_loads(smem_base, sn, c + 1, k0, t0);
            CP_COMMIT();
            CP_WAIT(1);        // chunk c's loads complete (c+1 may be pending)
        } else {
            CP_WAIT(0);
        }
        __syncthreads();
        FENCE_PROXY_ASYNC();
        if (wid == 0) {
            if (elect_one()) {
                uint64_t ad = MAKE_SMEM_DESC(smem_base + OFF_A(s));
                uint64_t bd = MAKE_SMEM_DESC(smem_base + OFF_B(s));
#pragma unroll
                for (int sub = 0; sub < 4; sub++)
                    mma_f16_ss(tmem_base, ad + sub * 2, bd + sub * 2, GEMM_IDESC,
                               (c > 0) || (sub > 0));
                TCGEN05_COMMIT(smem_base + OFF_MBAR + s * 8);
            }
        }
    }
    // drain: chunks 14 (mbar0) and 15 (mbar1)
    mbar_wait(smem_base + OFF_MBAR, ph[0]);
    mbar_wait(smem_base + OFF_MBAR + 8, ph[1]);
    TCGEN05_FENCE_AFTER();

    // ---- epilogue: two 128-col halves, each staged via SMEM then coalesced ----
    float* sg = (float*)(smem + 1024);   // 128*129*4 = 66048 B (dead buffers)
    float lsum = 0.0f;
    int sp = wid & 3;                    // TMEM subpartition (row group)
    int cg = wid >> 2;                   // column sub-group within half

#pragma unroll
    for (int hh = 0; hh < 2; hh++) {
        // TMEM -> SMEM (rows = k, cols = t within half)
#pragma unroll
        for (int q = 0; q < 2; q++) {
            uint32_t dr[32];
            TCGEN05_LD_X32(dr, tmem_base + hh * 128 + cg * 64 + q * 32);
            TCGEN05_WAIT_LD();
            float* dstp = sg + (sp * 32 + lid) * EPI_STRIDE + cg * 64 + q * 32;
#pragma unroll
            for (int j = 0; j < 32; j++) dstp[j] = __uint_as_float(dr[j]);
        }
        __syncthreads();

        // t-major coalesced writeout + loglik
#pragma unroll 4
        for (int p = 0; p < 64; p++) {
            int flat = p * 256 + tid;
            int kl = flat >> 7;           // 0..127
            int tl = flat & 127;          // lanes cover consecutive t
            int kg = k0 + kl;
            int tg = t0 + hh * 128 + tl;
            float mu = g_Mu0[kg];
            float x = sg[kl * EPI_STRIDE + tl];
            float l1 = softplus_fast(x);
            if (tg == 0) l1 = 0.0f;       // t == 0 branch
            size_t idx = (size_t)kg * NDIM + tg;
            if (full_out) {
                out_lam1[idx]  = l1;      // coalesced 128B/warp
                out_lams0[idx] = mu;
            }
            float o = obs[idx];           // coalesced
            lsum += o * log_fast(mu + l1 + 1e-5f) - mu - l1;
        }
        __syncthreads();
    }
    TCGEN05_FENCE_BEFORE();

    double* dred = (double*)(smem + 1024);
    dred[tid] = (double)lsum;
    __syncthreads();
    for (int off = 128; off > 0; off >>= 1) {
        if (tid < off) dred[tid] += dred[tid + off];
        __syncthreads();
    }
    if (tid == 0)
        g_partials[blockIdx.y * gridDim.x + blockIdx.x] = dred[0];

    if (tid == 0) {
        MBARRIER_INVAL(smem_base + OFF_MBAR);
        MBARRIER_INVAL(smem_base + OFF_MBAR + 8);
    }
    __syncthreads();
    if (wid == 0)
        TCGEN05_DEALLOC(tmem_base, 256);

#else  // ---------------- SIMT fallback (non-'a' PTX pass; never runs on bench GPU)
    int tx = tid & 15;
    int ty = tid >> 4;
    float acc[8][16];
#pragma unroll
    for (int i = 0; i < 8; i++)
#pragma unroll
        for (int j = 0; j < 16; j++) acc[i][j] = 0.0f;

    for (int jj = 0; jj < KDIM; jj++) {
        float a[8], b[16];
#pragma unroll
        for (int i = 0; i < 8; i++)
            a[i] = __bfloat162float(g_Abf[(size_t)(k0 + ty * 8 + i) * KDIM + jj]);
#pragma unroll
        for (int j = 0; j < 16; j++)
            b[j] = __bfloat162float(g_Gbf[(size_t)(t0 + tx * 16 + j) * KDIM + jj]);
#pragma unroll
        for (int i = 0; i < 8; i++)
#pragma unroll
            for (int j = 0; j < 16; j++) acc[i][j] = fmaf(a[i], b[j], acc[i][j]);
    }

    float lsum = 0.0f;
#pragma unroll
    for (int i = 0; i < 8; i++) {
        int k = k0 + ty * 8 + i;
        float mu = g_Mu0[k];
#pragma unroll
        for (int j = 0; j < 16; j++) {
            int t = t0 + tx * 16 + j;
            float lam = softplus_fast(acc[i][j] > 0.0f ? acc[i][j] : 0.0f);
            if (t == 0) lam = 0.0f;
            size_t idx = (size_t)k * NDIM + t;
            if (full_out) {
                out_lams0[idx] = mu;
                out_lam1[idx]  = lam;
            }
            float o = obs[idx];
            lsum += o * log_fast(mu + lam + 1e-5f) - mu - lam;
        }
    }
    double* dred = (double*)smem;
    dred[tid] = (double)lsum;
    __syncthreads();
    for (int off = 128; off > 0; off >>= 1) {
        if (tid < off) dred[tid] += dred[tid + off];
        __syncthreads();
    }
    if (tid == 0)
        g_partials[blockIdx.y * gridDim.x + blockIdx.x] = dred[0];
#endif
}

// ---------------------------------------------------------------------------
// Final reduction of 512 double partials -> out[0]
// ---------------------------------------------------------------------------
__global__ void final_reduce_kernel(float* __restrict__ out) {
    __shared__ double dred[256];
    int tid = threadIdx.x;
    double s = 0.0;
    for (int i = tid; i < 512; i += 256) s += g_partials[i];
    dred[tid] = s;
    __syncthreads();
    for (int off = 128; off > 0; off >>= 1) {
        if (tid < off) dred[tid] += dred[tid + off];
        __syncthreads();
    }
    if (tid == 0) out[0] = (float)dred[0];
}

// ---------------------------------------------------------------------------
extern "C" void kernel_launch(void* const* d_in, const int* in_sizes, int n_in,
                              void* d_out, int out_size) {
    const float* obs   = (const float*)d_in[0];   // [K, N]
    const float* Beta  = (const float*)d_in[1];   // [K]
    const float* Alpha = (const float*)d_in[2];   // [K, K]
    float* out = (float*)d_out;

    cudaFuncSetAttribute(gemm_kernel,
                         cudaFuncAttributeMaxDynamicSharedMemorySize, GEMM_SMEM);

    scan_fused_kernel<<<dim3(128, KDIM / 128), 256>>>(obs, Beta);
    convA_kernel<<<KDIM, 256>>>(Alpha);
    mu0_kernel<<<KDIM, 128>>>();

    dim3 grid(NDIM / GN, KDIM / GM);   // (64, 8)
    gemm_kernel<<<grid, 256, GEMM_SMEM>>>(obs, out, (long long)out_size);

    final_reduce_kernel<<<1, 256>>>(out);
}

// round 14
// speedup vs baseline: 3.4099x; 1.1199x over previous
#include <cuda_runtime.h>
#include <cuda_bf16.h>
#include <math.h>
#include <stdint.h>

#define KDIM 1024
#define NDIM 16384

// Feature gate: tcgen05 only exists on the sm_103a ('a'-feature) compile pass.
#if defined(__CUDA_ARCH_FEAT_SM103_ALL)
#define TC_PATH 1
#else
#define TC_PATH 0
#endif

// ---------------------------------------------------------------------------
// Scratch (device globals: allocation-free rule)
// ---------------------------------------------------------------------------
__device__ __align__(1024) __nv_bfloat16 g_Abf[(size_t)KDIM * KDIM]; // Alpha bf16 [k][j]
__device__ __align__(1024) __nv_bfloat16 g_Gbf[(size_t)NDIM * KDIM]; // G bf16 [t][j]
__device__ float  g_psum[(size_t)KDIM * 128];    // per-(row, t-chunk) partial sum
__device__ float  g_Mu0[KDIM];
__device__ double g_partials[512];

// ---------------------------------------------------------------------------
// PTX helpers (sm_103a)
// ---------------------------------------------------------------------------
__device__ __forceinline__ uint32_t smem_u32(const void* p) {
    uint32_t a;
    asm("{ .reg .u64 t; cvta.to.shared.u64 t, %1; cvt.u32.u64 %0, t; }" : "=r"(a) : "l"(p));
    return a;
}
__device__ __forceinline__ uint32_t elect_one() {
    uint32_t p;
    asm volatile("{\n\t.reg .pred p;\n\telect.sync _|p, 0xFFFFFFFF;\n\tselp.b32 %0, 1, 0, p;\n\t}" : "=r"(p));
    return p;
}
#define SMEM_SWIZZLE_128B(x) ((x) ^ (((x) >> 3) & 0x70))

static __device__ constexpr uint64_t SMEM_DESC_BASE_SW128 =
    (uint64_t(2) << 61) | (uint64_t(1) << 46) | (uint64_t(64) << 32) | (uint64_t(1) << 16);
#define MAKE_SMEM_DESC(a) (SMEM_DESC_BASE_SW128 | ((uint64_t)((a) >> 4) & 0x3FFF))

#define TCGEN05_ALLOC(sm, n) \
    asm volatile("tcgen05.alloc.cta_group::1.sync.aligned.shared::cta.b32 [%0], %1;" :: "r"((uint32_t)(sm)), "r"((uint32_t)(n)) : "memory")
#define TCGEN05_DEALLOC(tm, n) \
    asm volatile("tcgen05.dealloc.cta_group::1.sync.aligned.b32 %0, %1;" :: "r"(tm), "r"((uint32_t)(n)))
#define TCGEN05_RELINQ() \
    asm volatile("tcgen05.relinquish_alloc_permit.cta_group::1.sync.aligned;")
#define TCGEN05_COMMIT(mb) \
    asm volatile("tcgen05.commit.cta_group::1.mbarrier::arrive::one.shared::cluster.b64 [%0];" :: "r"((uint32_t)(mb)) : "memory")
#define TCGEN05_WAIT_LD()  asm volatile("tcgen05.wait::ld.sync.aligned;" ::: "memory")
#define TCGEN05_FENCE_AFTER() asm volatile("tcgen05.fence::after_thread_sync;" ::: "memory")
#define TCGEN05_FENCE_BEFORE() asm volatile("tcgen05.fence::before_thread_sync;" ::: "memory")
#define FENCE_PROXY_ASYNC() asm volatile("fence.proxy.async.shared::cta;" ::: "memory")
#define MBARRIER_INIT(mb, c) \
    asm volatile("mbarrier.init.shared.b64 [%0], %1;" :: "r"((uint32_t)(mb)), "r"((uint32_t)(c)) : "memory")
#define MBARRIER_INVAL(mb) \
    asm volatile("mbarrier.inval.shared.b64 [%0];" :: "r"((uint32_t)(mb)) : "memory")

__device__ __forceinline__ void mbar_wait(uint32_t addr, uint32_t parity) {
    asm volatile(
        "{\n\t.reg .pred P;\n\t"
        "LW%=:\n\t"
        "mbarrier.try_wait.parity.acquire.cta.shared::cta.b64 P, [%0], %1, 0x989680;\n\t"
        "@!P bra LW%=;\n\t}"
        :: "r"(addr), "r"(parity) : "memory");
}

__device__ __forceinline__ void cp_async16(uint32_t dst, const void* src) {
    asm volatile("cp.async.cg.shared.global [%0], [%1], 16;" :: "r"(dst), "l"(src));
}
#define CP_COMMIT() asm volatile("cp.async.commit_group;" ::: "memory")
#define CP_WAIT(n)  asm volatile("cp.async.wait_group %0;" :: "n"(n) : "memory")

// ---- fast transcendentals (MUFU): inputs guaranteed positive-domain ----
#define LOG2E_F 1.4426950408889634f
#define LN2_F   0.6931471805599453f
__device__ __forceinline__ float ex2_f(float x) {
    float r; asm("ex2.approx.f32 %0, %1;" : "=f"(r) : "f"(x)); return r;
}
__device__ __forceinline__ float lg2_f(float x) {
    float r; asm("lg2.approx.f32 %0, %1;" : "=f"(r) : "f"(x)); return r;
}
// softplus for x >= 0 (GEMM output is non-negative: Alpha>=0, G>=0)
__device__ __forceinline__ float softplus_fast(float x) {
    if (x > 20.0f) return x;
    return LN2_F * lg2_f(1.0f + ex2_f(x * LOG2E_F));
}
__device__ __forceinline__ float log_fast(float x) {
    return LN2_F * lg2_f(x);
}

#if TC_PATH
#define TCGEN05_LD_X32(r, tm) \
    asm volatile( \
        "tcgen05.ld.sync.aligned.32x32b.x32.b32 " \
        "{%0, %1, %2, %3, %4, %5, %6, %7, " \
        " %8, %9, %10, %11, %12, %13, %14, %15, " \
        " %16, %17, %18, %19, %20, %21, %22, %23, " \
        " %24, %25, %26, %27, %28, %29, %30, %31}, [%32];" \
        : "=r"((r)[0]),  "=r"((r)[1]),  "=r"((r)[2]),  "=r"((r)[3]), \
          "=r"((r)[4]),  "=r"((r)[5]),  "=r"((r)[6]),  "=r"((r)[7]), \
          "=r"((r)[8]),  "=r"((r)[9]),  "=r"((r)[10]), "=r"((r)[11]), \
          "=r"((r)[12]), "=r"((r)[13]), "=r"((r)[14]), "=r"((r)[15]), \
          "=r"((r)[16]), "=r"((r)[17]), "=r"((r)[18]), "=r"((r)[19]), \
          "=r"((r)[20]), "=r"((r)[21]), "=r"((r)[22]), "=r"((r)[23]), \
          "=r"((r)[24]), "=r"((r)[25]), "=r"((r)[26]), "=r"((r)[27]), \
          "=r"((r)[28]), "=r"((r)[29]), "=r"((r)[30]), "=r"((r)[31]) \
        : "r"(tm))

__device__ __forceinline__ void mma_f16_ss(uint32_t d_tmem, uint64_t a_desc,
                                           uint64_t b_desc, uint32_t idesc, bool en) {
    uint32_t e = en ? 1u : 0u;
    asm volatile(
        "{\n\t.reg .pred p;\n\t"
        "setp.ne.u32 p, %5, 0;\n\t"
        "tcgen05.mma.cta_group::1.kind::f16 [%0], %1, %2, %3, {%4, %4, %4, %4}, p;\n\t}"
        :: "r"(d_tmem), "l"(a_desc), "l"(b_desc), "r"(idesc), "r"(0u), "r"(e)
        : "memory");
}
#endif  // TC_PATH

// idesc: F32 accum, bf16 A/B, M=128, N=256
#define GEMM_IDESC 0x8400490u

// ---------------------------------------------------------------------------
// Fused scan kernel (proven round 12): warp-parallel affine scan, d^128 == 0.
// ---------------------------------------------------------------------------
__global__ void scan_fused_kernel(const float* __restrict__ obs,
                                  const float* __restrict__ Beta) {
    __shared__ uint32_t sg[128 * 64];   // 32 KB: [t 0..127][kpair 0..63] bf16x2
    int tid = threadIdx.x;
    int wid = tid >> 5;
    int lid = tid & 31;
    int c = blockIdx.x;          // 128-wide t chunk
    int kg = blockIdx.y;

    for (int p = 0; p < 16; p++) {
        int kk = wid * 16 + p;           // local row 0..127
        int row = kg * 128 + kk;
        float beta = Beta[row];
        float d = ex2_f(-beta * LOG2E_F);
        float d2 = d * d, d4 = d2 * d2;
        const float* rbase = obs + (size_t)row * NDIM;

        // --- previous-chunk carry -> S0 (S_start of chunk c) ---
        float S0 = 0.0f;
        if (c > 0) {
            float4 po = *(const float4*)(rbase + (c - 1) * 128 + lid * 4);
            float a = d4;
            float b = d * po.x;
            b = d * (b + po.y);
            b = d * (b + po.z);
            b = d * (b + po.w);
#pragma unroll
            for (int off = 1; off < 32; off <<= 1) {
                float aR = __shfl_down_sync(0xffffffffu, a, off);
                float bR = __shfl_down_sync(0xffffffffu, b, off);
                b = b * aR + bR;
                a = a * aR;
            }
            S0 = __shfl_sync(0xffffffffu, b, 0);
        }

        // --- current chunk: per-lane local affine + row-sum term ---
        float4 o = *(const float4*)(rbase + c * 128 + lid * 4);
        float ia = d4;
        float ib = d * o.x;
        ib = d * (ib + o.y);
        ib = d * (ib + o.z);
        ib = d * (ib + o.w);
        float suml = o.x + o.y + o.z + o.w;

#pragma unroll
        for (int off = 1; off < 32; off <<= 1) {
            float pa = __shfl_up_sync(0xffffffffu, ia, off);
            float pb = __shfl_up_sync(0xffffffffu, ib, off);
            if (lid >= off) {
                ib = pb * ia + ib;
                ia = pa * ia;
            }
        }
        float ea = __shfl_up_sync(0xffffffffu, ia, 1);
        float eb = __shfl_up_sync(0xffffffffu, ib, 1);
        if (lid == 0) { ea = 1.0f; eb = 0.0f; }
        float S = ea * S0 + eb;

        int kpair = kk >> 1, klow = kk & 1;
        char* sgb = (char*)sg;
#pragma unroll
        for (int i = 0; i < 4; i++) {
            int t = 4 * lid + i;
            int colp = (kpair + lid) & 63;
            *(__nv_bfloat16*)(sgb + t * 256 + colp * 4 + klow * 2) =
                __float2bfloat16_rn(beta * S);
            float oi = (i == 0) ? o.x : (i == 1) ? o.y : (i == 2) ? o.z : o.w;
            S = d * (S + oi);
        }

#pragma unroll
        for (int off = 16; off > 0; off >>= 1)
            suml += __shfl_down_sync(0xffffffffu, suml, off);
        if (lid == 0)
            g_psum[(size_t)row * 128 + c] = suml;
    }
    __syncthreads();

    uint32_t* gout = (uint32_t*)(g_Gbf + (size_t)c * 128 * KDIM + kg * 128);
#pragma unroll
    for (int p = 0; p < 32; p++) {
        int idx = tid + p * 256;
        int t = idx >> 6;
        int k2 = idx & 63;
        gout[(size_t)t * (KDIM / 2) + k2] = sg[t * 64 + ((k2 + (t >> 2)) & 63)];
    }
}

// ---------------------------------------------------------------------------
// Mu0 finalize
// ---------------------------------------------------------------------------
__global__ void mu0_kernel() {
    __shared__ float ss[128];
    int k = blockIdx.x;
    int tid = threadIdx.x;
    ss[tid] = g_psum[(size_t)k * 128 + tid];
    __syncthreads();
    for (int off = 64; off > 0; off >>= 1) {
        if (tid < off) ss[tid] += ss[tid + off];
        __syncthreads();
    }
    if (tid == 0)
        g_Mu0[k] = ss[0] / (float)(NDIM * 10) + 1e-5f;
}

// ---------------------------------------------------------------------------
// Alpha -> bf16
// ---------------------------------------------------------------------------
__global__ void convA_kernel(const float* __restrict__ Alpha) {
    size_t i4 = (size_t)blockIdx.x * blockDim.x + threadIdx.x;
    float4 v = ((const float4*)Alpha)[i4];
    __nv_bfloat162 lo, hi;
    lo.x = __float2bfloat16_rn(v.x); lo.y = __float2bfloat16_rn(v.y);
    hi.x = __float2bfloat16_rn(v.z); hi.y = __float2bfloat16_rn(v.w);
    ((__nv_bfloat162*)g_Abf)[i4 * 2]     = lo;
    ((__nv_bfloat162*)g_Abf)[i4 * 2 + 1] = hi;
}

// ---------------------------------------------------------------------------
// GEMM: 128(M=k) x 256(N=t) tile, GK=64, 2-stage cp.async mainloop, occ 2.
// Epilogue: four 64-col quarters; TMEM->SMEM stage + double-buffered cp.async
// obs prefetch; all global accesses coalesced, obs latency hidden.
// ---------------------------------------------------------------------------
#define GM 128
#define GN 256
#define GK 64
#define NCH (KDIM / GK)       // 16
#define STAGES 2

#define OFF_TPTR  0
#define OFF_MBAR  16          // two 8-byte mbarriers
#define STAGE_BYTES (16384 + 32768)          // A 16KB + B 32KB
#define OFF_A(s)  (1024 + (s) * STAGE_BYTES)
#define OFF_B(s)  (OFF_A(s) + 16384)

#define EPI_STRIDE 65                         // f32 stage stride (odd)
#define EPI_SG_BYTES (128 * EPI_STRIDE * 4)   // 33280
#define OBS_STRIDE 68                         // floats; 272B = 17*16 (16B-aligned rows)
#define OBS_BUF_BYTES (128 * OBS_STRIDE * 4)  // 34816
#define OFF_SG    1024
#define OFF_OBS(b) (1024 + EPI_SG_BYTES + (b) * OBS_BUF_BYTES)
#define GEMM_SMEM (1024 + EPI_SG_BYTES + 2 * OBS_BUF_BYTES)   // 103936; occ 2

#if TC_PATH
// async-load one K-chunk (A: 128x64, B: 256x64 bf16) into stage s
__device__ __forceinline__ void issue_loads(uint32_t smem_base, int s, int cn,
                                            int k0, int t0) {
    int tid = threadIdx.x;
    const __nv_bfloat16* asrc = g_Abf + (size_t)k0 * KDIM + cn * GK;
    const __nv_bfloat16* bsrc = g_Gbf + (size_t)t0 * KDIM + cn * GK;
#pragma unroll
    for (int p = 0; p < 4; p++) {
        int q = tid + p * 256;            // 0..1023
        int r = q >> 3;
        int cc = q & 7;
        uint32_t sw = SMEM_SWIZZLE_128B(r * 128 + cc * 16);
        cp_async16(smem_base + OFF_A(s) + sw, asrc + (size_t)r * KDIM + cc * 8);
    }
#pragma unroll
    for (int p = 0; p < 8; p++) {
        int q = tid + p * 256;            // 0..2047
        int r = q >> 3;                   // 0..255
        int cc = q & 7;
        uint32_t sw = SMEM_SWIZZLE_128B(r * 128 + cc * 16);
        cp_async16(smem_base + OFF_B(s) + sw, bsrc + (size_t)r * KDIM + cc * 8);
    }
}

// prefetch obs quarter: rows k0..k0+127, t range [tq, tq+64)
__device__ __forceinline__ void prefetch_obs(uint32_t smem_base, int buf,
                                             const float* obs, int k0, int tq) {
    int tid = threadIdx.x;
#pragma unroll
    for (int p = 0; p < 8; p++) {
        int idx = tid + p * 256;          // 0..2047
        int r = idx >> 4;                 // 0..127
        int cc = idx & 15;                // 16B chunk within 256B row
        cp_async16(smem_base + OFF_OBS(buf) + r * (OBS_STRIDE * 4) + cc * 16,
                   obs + (size_t)(k0 + r) * NDIM + tq + cc * 4);
    }
}
#endif

__global__ __launch_bounds__(256, 2)
void gemm_kernel(const float* __restrict__ obs,
                 float* __restrict__ out, long long out_size) {
    extern __shared__ char smem[];
    int tid = threadIdx.x;
    int t0 = blockIdx.x * GN;
    int k0 = blockIdx.y * GM;
    const long long KN = (long long)KDIM * NDIM;
    bool full_out = (out_size >= 1 + 2 * KN);
    // bases offset 4B from aligned allocation: 32-bit stores only
    float* out_lams0 = out + 1;
    float* out_lam1  = out + 1 + KN;

#if TC_PATH
    uint32_t smem_base = smem_u32(smem);
    int wid = tid >> 5;
    int lid = tid & 31;

    if (tid == 0) {
        MBARRIER_INIT(smem_base + OFF_MBAR, 1);
        MBARRIER_INIT(smem_base + OFF_MBAR + 8, 1);
    }
    if (wid == 0) {
        TCGEN05_ALLOC(smem_base + OFF_TPTR, 256);
        TCGEN05_RELINQ();
    }
    __syncthreads();
    uint32_t tmem_base;
    asm volatile("ld.shared.b32 %0, [%1];" : "=r"(tmem_base) : "r"(smem_base + OFF_TPTR));

    // prologue: preload chunk 0 into stage 0
    issue_loads(smem_base, 0, 0, k0, t0);
    CP_COMMIT();

    int ph[2] = {0, 0};
    for (int c = 0; c < NCH; c++) {
        int s = c & 1;
        if (c + 1 < NCH) {
            int sn = s ^ 1;
            if (c >= 1) {
                mbar_wait(smem_base + OFF_MBAR + sn * 8, ph[sn]);
                ph[sn] ^= 1;
            }
            issue_loads(smem_base, sn, c + 1, k0, t0);
            CP_COMMIT();
            CP_WAIT(1);
        } else {
            CP_WAIT(0);
        }
        __syncthreads();
        FENCE_PROXY_ASYNC();
        if (wid == 0) {
            if (elect_one()) {
                uint64_t ad = MAKE_SMEM_DESC(smem_base + OFF_A(s));
                uint64_t bd = MAKE_SMEM_DESC(smem_base + OFF_B(s));
#pragma unroll
                for (int sub = 0; sub < 4; sub++)
                    mma_f16_ss(tmem_base, ad + sub * 2, bd + sub * 2, GEMM_IDESC,
                               (c > 0) || (sub > 0));
                TCGEN05_COMMIT(smem_base + OFF_MBAR + s * 8);
            }
        }
    }
    // drain
    mbar_wait(smem_base + OFF_MBAR, ph[0]);
    mbar_wait(smem_base + OFF_MBAR + 8, ph[1]);
    TCGEN05_FENCE_AFTER();

    // ---- epilogue: 4 quarters of 64 cols, obs prefetch double-buffered ----
    float* sg = (float*)(smem + OFF_SG);
    float lsum = 0.0f;
    int sp = wid & 3;                    // TMEM subpartition (row group)
    int cg = wid >> 2;                   // 32-col group within quarter

    prefetch_obs(smem_base, 0, obs, k0, t0);
    CP_COMMIT();

#pragma unroll
    for (int q = 0; q < 4; q++) {
        // TMEM -> SMEM stage (64 cols; each warp: 32 rows x 32 cols)
        {
            uint32_t dr[32];
            TCGEN05_LD_X32(dr, tmem_base + q * 64 + cg * 32);
            TCGEN05_WAIT_LD();
            float* dstp = sg + (sp * 32 + lid) * EPI_STRIDE + cg * 32;
#pragma unroll
            for (int j = 0; j < 32; j++) dstp[j] = __uint_as_float(dr[j]);
        }
        // prefetch next quarter's obs into the other buffer
        if (q < 3) {
            prefetch_obs(smem_base, (q + 1) & 1, obs, k0, t0 + (q + 1) * 64);
            CP_COMMIT();
            CP_WAIT(1);       // quarter q's obs resident
        } else {
            CP_WAIT(0);
        }
        __syncthreads();

        const float* sobs = (const float*)(smem + OFF_OBS(q & 1));
        // process 128x64 elements, t-major coalesced stores
#pragma unroll 4
        for (int p = 0; p < 32; p++) {
            int flat = p * 256 + tid;
            int kl = flat >> 6;           // 0..127
            int tl = flat & 63;
            int kg = k0 + kl;
            int tg = t0 + q * 64 + tl;
            float mu = g_Mu0[kg];
            float x = sg[kl * EPI_STRIDE + tl];
            float l1 = softplus_fast(x);
            if (tg == 0) l1 = 0.0f;       // t == 0 branch
            size_t idx = (size_t)kg * NDIM + tg;
            if (full_out) {
                out_lam1[idx]  = l1;      // coalesced
                out_lams0[idx] = mu;
            }
            float o = sobs[kl * OBS_STRIDE + tl];
            lsum += o * log_fast(mu + l1 + 1e-5f) - mu - l1;
        }
        __syncthreads();
    }
    TCGEN05_FENCE_BEFORE();

    double* dred = (double*)(smem + OFF_SG);
    dred[tid] = (double)lsum;
    __syncthreads();
    for (int off = 128; off > 0; off >>= 1) {
        if (tid < off) dred[tid] += dred[tid + off];
        __syncthreads();
    }
    if (tid == 0)
        g_partials[blockIdx.y * gridDim.x + blockIdx.x] = dred[0];

    if (tid == 0) {
        MBARRIER_INVAL(smem_base + OFF_MBAR);
        MBARRIER_INVAL(smem_base + OFF_MBAR + 8);
    }
    __syncthreads();
    if (wid == 0)
        TCGEN05_DEALLOC(tmem_base, 256);

#else  // ---------------- SIMT fallback (non-'a' PTX pass; never runs on bench GPU)
    int tx = tid & 15;
    int ty = tid >> 4;
    float acc[8][16];
#pragma unroll
    for (int i = 0; i < 8; i++)
#pragma unroll
        for (int j = 0; j < 16; j++) acc[i][j] = 0.0f;

    for (int jj = 0; jj < KDIM; jj++) {
        float a[8], b[16];
#pragma unroll
        for (int i = 0; i < 8; i++)
            a[i] = __bfloat162float(g_Abf[(size_t)(k0 + ty * 8 + i) * KDIM + jj]);
#pragma unroll
        for (int j = 0; j < 16; j++)
            b[j] = __bfloat162float(g_Gbf[(size_t)(t0 + tx * 16 + j) * KDIM + jj]);
#pragma unroll
        for (int i = 0; i < 8; i++)
#pragma unroll
            for (int j = 0; j < 16; j++) acc[i][j] = fmaf(a[i], b[j], acc[i][j]);
    }

    float lsum = 0.0f;
#pragma unroll
    for (int i = 0; i < 8; i++) {
        int k = k0 + ty * 8 + i;
        float mu = g_Mu0[k];
#pragma unroll
        for (int j = 0; j < 16; j++) {
            int t = t0 + tx * 16 + j;
            float lam = softplus_fast(acc[i][j] > 0.0f ? acc[i][j] : 0.0f);
            if (t == 0) lam = 0.0f;
            size_t idx = (size_t)k * NDIM + t;
            if (full_out) {
                out_lams0[idx] = mu;
                out_lam1[idx]  = lam;
            }
            float o = obs[idx];
            lsum += o * log_fast(mu + lam + 1e-5f) - mu - lam;
        }
    }
    double* dred = (double*)smem;
    dred[tid] = (double)lsum;
    __syncthreads();
    for (int off = 128; off > 0; off >>= 1) {
        if (tid < off) dred[tid] += dred[tid + off];
        __syncthreads();
    }
    if (tid == 0)
        g_partials[blockIdx.y * gridDim.x + blockIdx.x] = dred[0];
#endif
}

// ---------------------------------------------------------------------------
// Final reduction of 512 double partials -> out[0]
// ---------------------------------------------------------------------------
__global__ void final_reduce_kernel(float* __restrict__ out) {
    __shared__ double dred[256];
    int tid = threadIdx.x;
    double s = 0.0;
    for (int i = tid; i < 512; i += 256) s += g_partials[i];
    dred[tid] = s;
    __syncthreads();
    for (int off = 128; off > 0; off >>= 1) {
        if (tid < off) dred[tid] += dred[tid + off];
        __syncthreads();
    }
    if (tid == 0) out[0] = (float)dred[0];
}

// ---------------------------------------------------------------------------
extern "C" void kernel_launch(void* const* d_in, const int* in_sizes, int n_in,
                              void* d_out, int out_size) {
    const float* obs   = (const float*)d_in[0];   // [K, N]
    const float* Beta  = (const float*)d_in[1];   // [K]
    const float* Alpha = (const float*)d_in[2];   // [K, K]
    float* out = (float*)d_out;

    cudaFuncSetAttribute(gemm_kernel,
                         cudaFuncAttributeMaxDynamicSharedMemorySize, GEMM_SMEM);

    scan_fused_kernel<<<dim3(128, KDIM / 128), 256>>>(obs, Beta);
    convA_kernel<<<KDIM, 256>>>(Alpha);
    mu0_kernel<<<KDIM, 128>>>();

    dim3 grid(NDIM / GN, KDIM / GM);   // (64, 8)
    gemm_kernel<<<grid, 256, GEMM_SMEM>>>(obs, out, (long long)out_size);

    final_reduce_kernel<<<1, 256>>>(out);
}